// round 14
// baseline (speedup 1.0000x reference)
#include <cuda_runtime.h>
#include <cuda_fp16.h>
#include <cstdint>

#define NHEADS 8
#define EMBED  512
#define HD     64
#define BATCH  4
#define SEQ    2048
#define STR    72   // smem tile stride in halves (144B rows)

// ---- scratch (allocation-free: __device__ globals) ----
__device__ __half g_Qh[BATCH*NHEADS*SEQ*HD];   // pre-scaled by log2(e)/sqrt(512)
__device__ __half g_Kh[BATCH*NHEADS*SEQ*HD];
__device__ __half g_Vh[BATCH*NHEADS*SEQ*HD];
__device__ __half g_Oh[BATCH*SEQ*EMBED];       // attention output pre-Wo (fp16)

__device__ __forceinline__ uint32_t saddr(const void* p){
    return (uint32_t)__cvta_generic_to_shared(p);
}
__device__ __forceinline__ void cp16(uint32_t d, const void* s){
    asm volatile("cp.async.cg.shared.global [%0], [%1], 16;\n" :: "r"(d), "l"(s));
}
#define CP_COMMIT() asm volatile("cp.async.commit_group;\n")
#define CP_WAIT0()  asm volatile("cp.async.wait_group 0;\n")
#define CP_WAIT1()  asm volatile("cp.async.wait_group 1;\n")

__device__ __forceinline__ void ldsm4(uint32_t* r, uint32_t a){
    asm volatile("ldmatrix.sync.aligned.m8n8.x4.shared.b16 {%0,%1,%2,%3}, [%4];\n"
        : "=r"(r[0]),"=r"(r[1]),"=r"(r[2]),"=r"(r[3]) : "r"(a));
}
__device__ __forceinline__ void ldsm4t(uint32_t* r, uint32_t a){
    asm volatile("ldmatrix.sync.aligned.m8n8.x4.trans.shared.b16 {%0,%1,%2,%3}, [%4];\n"
        : "=r"(r[0]),"=r"(r[1]),"=r"(r[2]),"=r"(r[3]) : "r"(a));
}
__device__ __forceinline__ void mma16(float* c, const uint32_t* a, const uint32_t* b){
    asm volatile(
        "mma.sync.aligned.m16n8k16.row.col.f32.f16.f16.f32 "
        "{%0,%1,%2,%3}, {%4,%5,%6,%7}, {%8,%9}, {%0,%1,%2,%3};\n"
        : "+f"(c[0]),"+f"(c[1]),"+f"(c[2]),"+f"(c[3])
        : "r"(a[0]),"r"(a[1]),"r"(a[2]),"r"(a[3]),"r"(b[0]),"r"(b[1]));
}
__device__ __forceinline__ float ex2f(float x){
    float y; asm("ex2.approx.f32 %0, %1;" : "=f"(y) : "f"(x)); return y;
}

// ============================================================================
// Kernel 1: fused QKV per-head projection via fp16 MMA.
// CTA = 128 seq rows x one (b,h) x one of Q/K/V (z). 8 warps x 16 rows.
// Q output pre-scaled by log2(e)/sqrt(512).
// ============================================================================
#define PJ_X  0
#define PJ_W  18432
#define PJ_TOTAL (18432 + 9216)

__global__ __launch_bounds__(256)
void proj_kernel(const float* __restrict__ Xq, const float* __restrict__ Xk,
                 const float* __restrict__ Xv,
                 const float* __restrict__ Wq, const float* __restrict__ Wk,
                 const float* __restrict__ Wv,
                 __half* __restrict__ Yq, __half* __restrict__ Yk,
                 __half* __restrict__ Yv){
    extern __shared__ char psm[];
    uint32_t xb = saddr(psm + PJ_X);
    uint32_t wb = saddr(psm + PJ_W);

    int z = blockIdx.z;
    const float* X = (z==0) ? Xq : (z==1) ? Xk : Xv;
    const float* W = (z==0) ? Wq : (z==1) ? Wk : Wv;
    __half*      Y = (z==0) ? Yq : (z==1) ? Yk : Yv;
    float sc = (z==0) ? 0.06375881311003162f : 1.0f;   // log2(e)/sqrt(512)

    int tid = threadIdx.x, lane = tid & 31, w = tid >> 5;
    int g = lane >> 2, t = lane & 3;
    int lrow16 = lane & 15;
    int lchunk = (lane >> 4) << 3;
    int bnrow  = (lane & 7) + ((lane >> 3) & 1) * 8;
    int bh = blockIdx.y; int b = bh >> 3; int h = bh & 7;
    int s0 = blockIdx.x * 128;

    #pragma unroll
    for (int j = 0; j < 8; j++){
        int lin = tid + j*256;
        int row = lin >> 4, c4 = (lin & 15) << 2;
        float4 v = *reinterpret_cast<const float4*>(
            X + (((size_t)b*SEQ + s0 + row)*NHEADS + h)*HD + c4);
        __half2 h0 = __floats2half2_rn(v.x, v.y);
        __half2 h1 = __floats2half2_rn(v.z, v.w);
        uint2 u; u.x = *(uint32_t*)&h0; u.y = *(uint32_t*)&h1;
        *reinterpret_cast<uint2*>(psm + PJ_X + (row*STR + c4)*2) = u;
    }
    #pragma unroll
    for (int j = 0; j < 4; j++){
        int lin = tid + j*256;
        int row = lin >> 4, c4 = (lin & 15) << 2;
        float4 v = *reinterpret_cast<const float4*>(W + (size_t)row*64 + c4);
        __half2 h0 = __floats2half2_rn(v.x, v.y);
        __half2 h1 = __floats2half2_rn(v.z, v.w);
        uint2 u; u.x = *(uint32_t*)&h0; u.y = *(uint32_t*)&h1;
        *reinterpret_cast<uint2*>(psm + PJ_W + (row*STR + c4)*2) = u;
    }
    __syncthreads();

    float c[8][4];
    #pragma unroll
    for (int ni=0; ni<8; ni++){ c[ni][0]=0.f; c[ni][1]=0.f; c[ni][2]=0.f; c[ni][3]=0.f; }
    #pragma unroll
    for (int k16 = 0; k16 < 4; k16++){
        uint32_t a[4];
        ldsm4(a, xb + ((w*16+lrow16)*STR + k16*16 + lchunk)*2);
        uint32_t bq[4][4];
        #pragma unroll
        for (int nq=0; nq<4; nq++)
            ldsm4(bq[nq], wb + ((nq*16+bnrow)*STR + k16*16 + lchunk)*2);
        #pragma unroll
        for (int nq=0; nq<4; nq++)
            #pragma unroll
            for (int sub=0; sub<2; sub++){
                uint32_t bb[2] = { bq[nq][sub], bq[nq][sub+2] };
                mma16(c[nq*2+sub], a, bb);
            }
    }

    __half* Yp = Y + ((size_t)bh*SEQ + s0 + w*16)*HD;
    #pragma unroll
    for (int ni=0; ni<8; ni++){
        int cl = ni*8 + 2*t;
        __half2 o0 = __floats2half2_rn(c[ni][0]*sc, c[ni][1]*sc);
        __half2 o1 = __floats2half2_rn(c[ni][2]*sc, c[ni][3]*sc);
        *reinterpret_cast<__half2*>(Yp + (size_t)g*HD + cl)     = o0;
        *reinterpret_cast<__half2*>(Yp + (size_t)(g+8)*HD + cl) = o1;
    }
}

// ============================================================================
// Kernel 2: two-pass fused attention, 256-row q-tiles, 16 warps x 16 q-rows.
// 3-stage cp.async ring, hoisted Q fragments, register-direct PV.
// grid (8, 32), 512 threads, 100352 B smem -> 1 CTA/SM (16 warps, same as
// the previous 2x256 config, but half the chip-wide K/V traffic).
// ============================================================================
#define SM_QH   0
#define SM_K0   36864
#define SM_V0   64512
#define SM_MSK  92160
#define SM_TOTAL 100352
#define KBUF    9216

__global__ __launch_bounds__(512, 1)
void attn_kernel(const int* __restrict__ mask, float* __restrict__ attn){
    extern __shared__ char smc[];
    int* Msk = (int*)(smc + SM_MSK);
    uint32_t qb = saddr(smc + SM_QH);
    uint32_t kbuf[3] = { saddr(smc + SM_K0), saddr(smc + SM_K0 + KBUF),
                         saddr(smc + SM_K0 + 2*KBUF) };
    uint32_t vbuf[3] = { saddr(smc + SM_V0), saddr(smc + SM_V0 + KBUF),
                         saddr(smc + SM_V0 + 2*KBUF) };

    int tid = threadIdx.x, lane = tid & 31, w = tid >> 5;   // w: 0..15
    int g = lane >> 2, t = lane & 3;
    int lrow16 = lane & 15;
    int lchunk = (lane >> 4) << 3;
    int bnrow  = (lane & 7) + ((lane >> 3) & 1) * 8;
    int bh = blockIdx.y, b = bh >> 3, h = bh & 7;
    int q0 = blockIdx.x * 256;
    const __half* Qp = g_Qh + (size_t)bh*SEQ*HD;
    const __half* Kp = g_Kh + (size_t)bh*SEQ*HD;
    const __half* Vp = g_Vh + (size_t)bh*SEQ*HD;
    const int* mrow_g = mask + (size_t)b*SEQ;
    int row0 = w*16 + g;                                     // 0..255

    // per-thread K/V tile load slot: 64 rows x 8 chunks(16B) = 512 slots
    int ldr = tid >> 3, ldc = tid & 7;
    uint32_t so = (ldr*STR + ldc*8)*2;
    size_t   go = (size_t)ldr*HD + ldc*8;

    // ---- Q tile (256 rows, sync) + mask row (sync) ----
    #pragma unroll
    for (int j = 0; j < 4; j++){
        int lin = tid + j*512;
        int row = lin >> 3, ch = lin & 7;
        uint4 v = *reinterpret_cast<const uint4*>(Qp + (size_t)(q0+row)*HD + ch*8);
        *reinterpret_cast<uint4*>(smc + SM_QH + row*(STR*2) + ch*16) = v;
    }
    {
        int4 v = *reinterpret_cast<const int4*>(mrow_g + tid*4);
        *reinterpret_cast<int4*>(Msk + tid*4) = v;
    }

    // prologue: K(0), K(1)
    cp16(kbuf[0] + so, Kp + go);
    CP_COMMIT();
    cp16(kbuf[1] + so, Kp + 64*HD + go);
    CP_COMMIT();

    __syncthreads();   // Q + mask visible

    // ---- hoisted Q fragments ----
    uint32_t aq[4][4];
    #pragma unroll
    for (int k16 = 0; k16 < 4; k16++)
        ldsm4(aq[k16], qb + ((w*16+lrow16)*STR + k16*16 + lchunk)*2);

    // ---------------- PASS 1: rowsum of ex2(QK) ----------------
    float ls0a = 0.f, ls0b = 0.f, ls1a = 0.f, ls1b = 0.f;
    int cur = 0, pf = 2;
    for (int kt = 0; kt < 32; kt++){
        if (kt == 31) { CP_WAIT0(); } else { CP_WAIT1(); }
        __syncthreads();
        if (kt < 30){
            cp16(kbuf[pf] + so, Kp + (size_t)(kt+2)*64*HD + go);
            CP_COMMIT();
        }
        uint32_t kba = kbuf[cur];
        int kb0 = kt*64;

        float c[8][4];
        #pragma unroll
        for (int ni=0; ni<8; ni++){ c[ni][0]=0.f; c[ni][1]=0.f; c[ni][2]=0.f; c[ni][3]=0.f; }
        #pragma unroll
        for (int k16 = 0; k16 < 4; k16++){
            uint32_t bq[4][4];
            #pragma unroll
            for (int nq=0; nq<4; nq++)
                ldsm4(bq[nq], kba + ((nq*16+bnrow)*STR + k16*16 + lchunk)*2);
            #pragma unroll
            for (int nq=0; nq<4; nq++)
                #pragma unroll
                for (int sub=0; sub<2; sub++){
                    uint32_t bb[2] = { bq[nq][sub], bq[nq][sub+2] };
                    mma16(c[nq*2+sub], aq[k16], bb);
                }
        }
        #pragma unroll
        for (int ni=0; ni<8; ni++){
            int col = kb0 + ni*8 + 2*t;
            int2 mm = *reinterpret_cast<const int2*>(Msk + col);
            bool m0 = (mm.x == 0), m1 = (mm.y == 0);
            if (ni & 1){
                ls0b += (m0?0.f:ex2f(c[ni][0])) + (m1?0.f:ex2f(c[ni][1]));
                ls1b += (m0?0.f:ex2f(c[ni][2])) + (m1?0.f:ex2f(c[ni][3]));
            } else {
                ls0a += (m0?0.f:ex2f(c[ni][0])) + (m1?0.f:ex2f(c[ni][1]));
                ls1a += (m0?0.f:ex2f(c[ni][2])) + (m1?0.f:ex2f(c[ni][3]));
            }
        }
        cur = (cur==2) ? 0 : cur+1;
        pf  = (pf==2)  ? 0 : pf+1;
    }
    float lsum0 = ls0a + ls0b, lsum1 = ls1a + ls1b;
    lsum0 += __shfl_xor_sync(0xffffffffu, lsum0, 1);
    lsum0 += __shfl_xor_sync(0xffffffffu, lsum0, 2);
    lsum1 += __shfl_xor_sync(0xffffffffu, lsum1, 1);
    lsum1 += __shfl_xor_sync(0xffffffffu, lsum1, 2);
    float il0 = 1.0f / lsum0;
    float il1 = 1.0f / lsum1;

    __syncthreads();   // pass-1 buffers free

    // ---------------- PASS 2: normalized P -> attn + PV ----------------
    float co[8][4];
    #pragma unroll
    for (int ni=0; ni<8; ni++){ co[ni][0]=0.f; co[ni][1]=0.f; co[ni][2]=0.f; co[ni][3]=0.f; }

    cp16(kbuf[0] + so, Kp + go);
    cp16(vbuf[0] + so, Vp + go);
    CP_COMMIT();
    cp16(kbuf[1] + so, Kp + 64*HD + go);
    cp16(vbuf[1] + so, Vp + 64*HD + go);
    CP_COMMIT();

    float* ar0 = attn + ((size_t)bh*SEQ + q0 + row0)*SEQ;
    float* ar1 = ar0 + (size_t)8*SEQ;

    cur = 0; pf = 2;
    for (int kt = 0; kt < 32; kt++){
        if (kt == 31) { CP_WAIT0(); } else { CP_WAIT1(); }
        __syncthreads();
        if (kt < 30){
            cp16(kbuf[pf] + so, Kp + (size_t)(kt+2)*64*HD + go);
            cp16(vbuf[pf] + so, Vp + (size_t)(kt+2)*64*HD + go);
            CP_COMMIT();
        }
        uint32_t kba = kbuf[cur], vba = vbuf[cur];
        int kb0 = kt*64;

        float c[8][4];
        #pragma unroll
        for (int ni=0; ni<8; ni++){ c[ni][0]=0.f; c[ni][1]=0.f; c[ni][2]=0.f; c[ni][3]=0.f; }
        #pragma unroll
        for (int k16 = 0; k16 < 4; k16++){
            uint32_t bq[4][4];
            #pragma unroll
            for (int nq=0; nq<4; nq++)
                ldsm4(bq[nq], kba + ((nq*16+bnrow)*STR + k16*16 + lchunk)*2);
            #pragma unroll
            for (int nq=0; nq<4; nq++)
                #pragma unroll
                for (int sub=0; sub<2; sub++){
                    uint32_t bb[2] = { bq[nq][sub], bq[nq][sub+2] };
                    mma16(c[nq*2+sub], aq[k16], bb);
                }
        }

        uint32_t ph0[8], ph1[8];
        #pragma unroll
        for (int ni=0; ni<8; ni++){
            int cl = ni*8 + 2*t;
            int col = kb0 + cl;
            int2 mm = *reinterpret_cast<const int2*>(Msk + col);
            bool m0 = (mm.x == 0), m1 = (mm.y == 0);
            float p00 = m0 ? 0.f : ex2f(c[ni][0]) * il0;
            float p01 = m1 ? 0.f : ex2f(c[ni][1]) * il0;
            float p10 = m0 ? 0.f : ex2f(c[ni][2]) * il1;
            float p11 = m1 ? 0.f : ex2f(c[ni][3]) * il1;
            __stcs(reinterpret_cast<float2*>(ar0 + col), make_float2(p00, p01));
            __stcs(reinterpret_cast<float2*>(ar1 + col), make_float2(p10, p11));
            __half2 h0v = __floats2half2_rn(p00, p01);
            __half2 h1v = __floats2half2_rn(p10, p11);
            ph0[ni] = *(uint32_t*)&h0v;
            ph1[ni] = *(uint32_t*)&h1v;
        }

        #pragma unroll
        for (int k16 = 0; k16 < 4; k16++){
            uint32_t ap[4] = { ph0[2*k16], ph1[2*k16], ph0[2*k16+1], ph1[2*k16+1] };
            #pragma unroll
            for (int ni2 = 0; ni2 < 4; ni2++){
                uint32_t bv4[4];
                ldsm4t(bv4, vba + ((k16*16+lrow16)*STR + ni2*16 + lchunk)*2);
                mma16(co[ni2*2],   ap, bv4);
                mma16(co[ni2*2+1], ap, bv4+2);
            }
        }
        cur = (cur==2) ? 0 : cur+1;
        pf  = (pf==2)  ? 0 : pf+1;
    }

    __half* Op = g_Oh + ((size_t)b*SEQ + q0 + w*16)*EMBED + h*HD;
    #pragma unroll
    for (int ni=0; ni<8; ni++){
        int cl = ni*8 + 2*t;
        __half2 o0 = __floats2half2_rn(co[ni][0], co[ni][1]);
        __half2 o1 = __floats2half2_rn(co[ni][2], co[ni][3]);
        *reinterpret_cast<__half2*>(Op + (size_t)g*EMBED + cl)     = o0;
        *reinterpret_cast<__half2*>(Op + (size_t)(g+8)*EMBED + cl) = o1;
    }
}

// ============================================================================
// Kernel 3: out = g_Oh @ Wo.T + bo   (M=8192, N=512, K=512)  fp16 MMA
// ============================================================================
#define OP_SMEM_BYTES (128*STR*2 + 64*STR*2)

__global__ __launch_bounds__(256)
void oproj_kernel(const float* __restrict__ Wo, const float* __restrict__ bo,
                  float* __restrict__ out){
    extern __shared__ char osmc[];
    uint32_t ab = saddr(osmc);
    uint32_t bb_ = saddr(osmc + 128*STR*2);
    __half* Bh = (__half*)(osmc + 128*STR*2);

    int tid = threadIdx.x, lane = tid & 31, warp = tid >> 5;
    int wm = warp >> 1, wn = warp & 1, rm = wm*32;
    int g = lane >> 2, t = lane & 3;
    int lrow16 = lane & 15;
    int lchunk = (lane >> 4) << 3;
    int bnrow  = (lane & 7) + ((lane >> 3) & 1) * 8;
    int n0 = blockIdx.x * 64;
    int m0 = blockIdx.y * 128;

    float c[2][4][4];
    #pragma unroll
    for (int mi=0;mi<2;mi++)
        #pragma unroll
        for (int ni=0;ni<4;ni++)
            { c[mi][ni][0]=0.f;c[mi][ni][1]=0.f;c[mi][ni][2]=0.f;c[mi][ni][3]=0.f; }

    const __half* Ap = g_Oh + (size_t)m0*EMBED;

    for (int k0 = 0; k0 < 512; k0 += 64){
        __syncthreads();
        #pragma unroll
        for (int j = 0; j < 4; j++){
            int lin = tid + j*256;
            int row = lin >> 3, ch = lin & 7;
            uint4 v = *reinterpret_cast<const uint4*>(Ap + (size_t)row*EMBED + k0 + ch*8);
            *reinterpret_cast<uint4*>(osmc + row*(STR*2) + ch*16) = v;
        }
        #pragma unroll
        for (int j = 0; j < 2; j++){
            int lin = tid + j*256;
            int row = lin >> 3, c8 = (lin & 7) * 8;
            const float* src = Wo + (size_t)(n0+row)*512 + k0 + c8;
            float4 v0 = *reinterpret_cast<const float4*>(src);
            float4 v1 = *reinterpret_cast<const float4*>(src + 4);
            __half2 h0 = __floats2half2_rn(v0.x, v0.y);
            __half2 h1 = __floats2half2_rn(v0.z, v0.w);
            __half2 h2 = __floats2half2_rn(v1.x, v1.y);
            __half2 h3 = __floats2half2_rn(v1.z, v1.w);
            uint4 u; u.x = *(uint32_t*)&h0; u.y = *(uint32_t*)&h1;
            u.z = *(uint32_t*)&h2; u.w = *(uint32_t*)&h3;
            *reinterpret_cast<uint4*>((char*)Bh + row*(STR*2) + c8*2) = u;
        }
        __syncthreads();

        #pragma unroll
        for (int k16 = 0; k16 < 4; k16++){
            uint32_t a[2][4];
            #pragma unroll
            for (int mi=0; mi<2; mi++)
                ldsm4(a[mi], ab + ((rm+mi*16+lrow16)*STR + k16*16 + lchunk)*2);
            uint32_t bq[2][4];
            #pragma unroll
            for (int pr=0; pr<2; pr++)
                ldsm4(bq[pr], bb_ + ((wn*32+pr*16+bnrow)*STR + k16*16 + lchunk)*2);
            #pragma unroll
            for (int mi=0; mi<2; mi++)
                #pragma unroll
                for (int pr=0; pr<2; pr++)
                    #pragma unroll
                    for (int sub=0; sub<2; sub++){
                        uint32_t bb2[2] = { bq[pr][sub], bq[pr][sub+2] };
                        mma16(c[mi][pr*2+sub], a[mi], bb2);
                    }
        }
    }
    #pragma unroll
    for (int mi=0;mi<2;mi++)
        #pragma unroll
        for (int half=0; half<2; half++){
            int row = rm + mi*16 + half*8 + g;
            #pragma unroll
            for (int ni=0; ni<4; ni++){
                int col = wn*32 + ni*8 + 2*t;
                float2 bv = *reinterpret_cast<const float2*>(bo + n0 + col);
                *reinterpret_cast<float2*>(out + (size_t)(m0+row)*512 + n0 + col) =
                    make_float2(c[mi][ni][half*2] + bv.x, c[mi][ni][half*2+1] + bv.y);
            }
        }
}

// ============================================================================
// launch
// ============================================================================
extern "C" void kernel_launch(void* const* d_in, const int* in_sizes, int n_in,
                              void* d_out, int out_size){
    (void)in_sizes; (void)n_in; (void)out_size;
    const float* values = (const float*)d_in[0];
    const float* keys   = (const float*)d_in[1];
    const float* query  = (const float*)d_in[2];
    const int*   mask   = (const int*)d_in[3];
    const float* Wv     = (const float*)d_in[4];
    const float* Wk     = (const float*)d_in[5];
    const float* Wq     = (const float*)d_in[6];
    const float* Wo     = (const float*)d_in[7];
    const float* bo     = (const float*)d_in[8];

    float* out  = (float*)d_out;                              // [B,S,E]
    float* attn = out + (size_t)BATCH*SEQ*EMBED;              // [B,H,S,S]

    __half *qptr, *kptr, *vptr;
    cudaGetSymbolAddress((void**)&qptr, g_Qh);
    cudaGetSymbolAddress((void**)&kptr, g_Kh);
    cudaGetSymbolAddress((void**)&vptr, g_Vh);

    cudaFuncSetAttribute(attn_kernel, cudaFuncAttributeMaxDynamicSharedMemorySize,
                         SM_TOTAL);
    cudaFuncSetAttribute(oproj_kernel, cudaFuncAttributeMaxDynamicSharedMemorySize,
                         OP_SMEM_BYTES);
    cudaFuncSetAttribute(proj_kernel, cudaFuncAttributeMaxDynamicSharedMemorySize,
                         PJ_TOTAL);

    proj_kernel<<<dim3(SEQ/128, BATCH*NHEADS, 3), 256, PJ_TOTAL>>>(
        query, keys, values, Wq, Wk, Wv, qptr, kptr, vptr);

    attn_kernel<<<dim3(SEQ/256, BATCH*NHEADS), 512, SM_TOTAL>>>(mask, attn);

    oproj_kernel<<<dim3(EMBED/64, (BATCH*SEQ)/128), 256, OP_SMEM_BYTES>>>(Wo, bo, out);
}

// round 15
// speedup vs baseline: 1.0359x; 1.0359x over previous
#include <cuda_runtime.h>
#include <cuda_fp16.h>
#include <cstdint>

#define NHEADS 8
#define EMBED  512
#define HD     64
#define BATCH  4
#define SEQ    2048
#define STR    72   // smem tile stride in halves (144B rows)

// ---- scratch (allocation-free: __device__ globals) ----
__device__ __half g_Qh[BATCH*NHEADS*SEQ*HD];   // pre-scaled by log2(e)/sqrt(512)
__device__ __half g_Kh[BATCH*NHEADS*SEQ*HD];
__device__ __half g_Vh[BATCH*NHEADS*SEQ*HD];
__device__ __half g_Oh[BATCH*SEQ*EMBED];       // attention output pre-Wo (fp16)

__device__ __forceinline__ uint32_t saddr(const void* p){
    return (uint32_t)__cvta_generic_to_shared(p);
}
__device__ __forceinline__ void cp16(uint32_t d, const void* s){
    asm volatile("cp.async.cg.shared.global [%0], [%1], 16;\n" :: "r"(d), "l"(s));
}
#define CP_COMMIT() asm volatile("cp.async.commit_group;\n")
#define CP_WAIT0()  asm volatile("cp.async.wait_group 0;\n")
#define CP_WAIT1()  asm volatile("cp.async.wait_group 1;\n")

__device__ __forceinline__ void ldsm4(uint32_t* r, uint32_t a){
    asm volatile("ldmatrix.sync.aligned.m8n8.x4.shared.b16 {%0,%1,%2,%3}, [%4];\n"
        : "=r"(r[0]),"=r"(r[1]),"=r"(r[2]),"=r"(r[3]) : "r"(a));
}
__device__ __forceinline__ void ldsm4t(uint32_t* r, uint32_t a){
    asm volatile("ldmatrix.sync.aligned.m8n8.x4.trans.shared.b16 {%0,%1,%2,%3}, [%4];\n"
        : "=r"(r[0]),"=r"(r[1]),"=r"(r[2]),"=r"(r[3]) : "r"(a));
}
__device__ __forceinline__ void mma16(float* c, const uint32_t* a, const uint32_t* b){
    asm volatile(
        "mma.sync.aligned.m16n8k16.row.col.f32.f16.f16.f32 "
        "{%0,%1,%2,%3}, {%4,%5,%6,%7}, {%8,%9}, {%0,%1,%2,%3};\n"
        : "+f"(c[0]),"+f"(c[1]),"+f"(c[2]),"+f"(c[3])
        : "r"(a[0]),"r"(a[1]),"r"(a[2]),"r"(a[3]),"r"(b[0]),"r"(b[1]));
}
__device__ __forceinline__ float ex2f(float x){
    float y; asm("ex2.approx.f32 %0, %1;" : "=f"(y) : "f"(x)); return y;
}

// ============================================================================
// Kernel 1: fused QKV per-head projection via fp16 MMA.
// CTA = 128 seq rows x one (b,h) x one of Q/K/V (z). 8 warps x 16 rows.
// Q output pre-scaled by log2(e)/sqrt(512).
// ============================================================================
#define PJ_X  0
#define PJ_W  18432
#define PJ_TOTAL (18432 + 9216)

__global__ __launch_bounds__(256)
void proj_kernel(const float* __restrict__ Xq, const float* __restrict__ Xk,
                 const float* __restrict__ Xv,
                 const float* __restrict__ Wq, const float* __restrict__ Wk,
                 const float* __restrict__ Wv,
                 __half* __restrict__ Yq, __half* __restrict__ Yk,
                 __half* __restrict__ Yv){
    extern __shared__ char psm[];
    uint32_t xb = saddr(psm + PJ_X);
    uint32_t wb = saddr(psm + PJ_W);

    int z = blockIdx.z;
    const float* X = (z==0) ? Xq : (z==1) ? Xk : Xv;
    const float* W = (z==0) ? Wq : (z==1) ? Wk : Wv;
    __half*      Y = (z==0) ? Yq : (z==1) ? Yk : Yv;
    float sc = (z==0) ? 0.06375881311003162f : 1.0f;   // log2(e)/sqrt(512)

    int tid = threadIdx.x, lane = tid & 31, w = tid >> 5;
    int g = lane >> 2, t = lane & 3;
    int lrow16 = lane & 15;
    int lchunk = (lane >> 4) << 3;
    int bnrow  = (lane & 7) + ((lane >> 3) & 1) * 8;
    int bh = blockIdx.y; int b = bh >> 3; int h = bh & 7;
    int s0 = blockIdx.x * 128;

    #pragma unroll
    for (int j = 0; j < 8; j++){
        int lin = tid + j*256;
        int row = lin >> 4, c4 = (lin & 15) << 2;
        float4 v = *reinterpret_cast<const float4*>(
            X + (((size_t)b*SEQ + s0 + row)*NHEADS + h)*HD + c4);
        __half2 h0 = __floats2half2_rn(v.x, v.y);
        __half2 h1 = __floats2half2_rn(v.z, v.w);
        uint2 u; u.x = *(uint32_t*)&h0; u.y = *(uint32_t*)&h1;
        *reinterpret_cast<uint2*>(psm + PJ_X + (row*STR + c4)*2) = u;
    }
    #pragma unroll
    for (int j = 0; j < 4; j++){
        int lin = tid + j*256;
        int row = lin >> 4, c4 = (lin & 15) << 2;
        float4 v = *reinterpret_cast<const float4*>(W + (size_t)row*64 + c4);
        __half2 h0 = __floats2half2_rn(v.x, v.y);
        __half2 h1 = __floats2half2_rn(v.z, v.w);
        uint2 u; u.x = *(uint32_t*)&h0; u.y = *(uint32_t*)&h1;
        *reinterpret_cast<uint2*>(psm + PJ_W + (row*STR + c4)*2) = u;
    }
    __syncthreads();

    float c[8][4];
    #pragma unroll
    for (int ni=0; ni<8; ni++){ c[ni][0]=0.f; c[ni][1]=0.f; c[ni][2]=0.f; c[ni][3]=0.f; }
    #pragma unroll
    for (int k16 = 0; k16 < 4; k16++){
        uint32_t a[4];
        ldsm4(a, xb + ((w*16+lrow16)*STR + k16*16 + lchunk)*2);
        uint32_t bq[4][4];
        #pragma unroll
        for (int nq=0; nq<4; nq++)
            ldsm4(bq[nq], wb + ((nq*16+bnrow)*STR + k16*16 + lchunk)*2);
        #pragma unroll
        for (int nq=0; nq<4; nq++)
            #pragma unroll
            for (int sub=0; sub<2; sub++){
                uint32_t bb[2] = { bq[nq][sub], bq[nq][sub+2] };
                mma16(c[nq*2+sub], a, bb);
            }
    }

    __half* Yp = Y + ((size_t)bh*SEQ + s0 + w*16)*HD;
    #pragma unroll
    for (int ni=0; ni<8; ni++){
        int cl = ni*8 + 2*t;
        __half2 o0 = __floats2half2_rn(c[ni][0]*sc, c[ni][1]*sc);
        __half2 o1 = __floats2half2_rn(c[ni][2]*sc, c[ni][3]*sc);
        *reinterpret_cast<__half2*>(Yp + (size_t)g*HD + cl)     = o0;
        *reinterpret_cast<__half2*>(Yp + (size_t)(g+8)*HD + cl) = o1;
    }
}

// ============================================================================
// Kernel 2: two-pass fused attention, 8 warps x 16 q-rows, 3-stage cp.async
// ring. Q fragments hoisted out of the k-loops (register-resident),
// 4-way lsum accumulators, int2 mask loads.
// grid (16, 32), 256 threads, 81920 B smem -> 2 CTAs/SM.
// ============================================================================
#define SM_QH   0
#define SM_K0   18432
#define SM_V0   46080
#define SM_MSK  73728
#define SM_TOTAL 81920
#define KBUF    9216

__global__ __launch_bounds__(256, 2)
void attn_kernel(const int* __restrict__ mask, float* __restrict__ attn){
    extern __shared__ char smc[];
    int* Msk = (int*)(smc + SM_MSK);
    uint32_t qb = saddr(smc + SM_QH);
    uint32_t kbuf[3] = { saddr(smc + SM_K0), saddr(smc + SM_K0 + KBUF),
                         saddr(smc + SM_K0 + 2*KBUF) };
    uint32_t vbuf[3] = { saddr(smc + SM_V0), saddr(smc + SM_V0 + KBUF),
                         saddr(smc + SM_V0 + 2*KBUF) };

    int tid = threadIdx.x, lane = tid & 31, w = tid >> 5;
    int g = lane >> 2, t = lane & 3;
    int lrow16 = lane & 15;
    int lchunk = (lane >> 4) << 3;
    int bnrow  = (lane & 7) + ((lane >> 3) & 1) * 8;
    int bh = blockIdx.y, b = bh >> 3, h = bh & 7;
    int q0 = blockIdx.x * 128;
    const __half* Qp = g_Qh + (size_t)bh*SEQ*HD;
    const __half* Kp = g_Kh + (size_t)bh*SEQ*HD;
    const __half* Vp = g_Vh + (size_t)bh*SEQ*HD;
    const int* mrow_g = mask + (size_t)b*SEQ;
    int row0 = w*16 + g;

    int ldr0 = tid >> 3, ldc = tid & 7;
    int ldr1 = ldr0 + 32;
    uint32_t so0 = (ldr0*STR + ldc*8)*2;
    uint32_t so1 = (ldr1*STR + ldc*8)*2;
    size_t   go0 = (size_t)ldr0*HD + ldc*8;
    size_t   go1 = (size_t)ldr1*HD + ldc*8;

    // ---- Q tile (sync) + mask row (sync) ----
    #pragma unroll
    for (int j = 0; j < 4; j++){
        int lin = tid + j*256;
        int row = lin >> 3, ch = lin & 7;
        uint4 v = *reinterpret_cast<const uint4*>(Qp + (size_t)(q0+row)*HD + ch*8);
        *reinterpret_cast<uint4*>(smc + SM_QH + row*(STR*2) + ch*16) = v;
    }
    #pragma unroll
    for (int j = 0; j < 2; j++){
        int lin = tid + j*256;
        int4 v = *reinterpret_cast<const int4*>(mrow_g + lin*4);
        *reinterpret_cast<int4*>(Msk + lin*4) = v;
    }

    // prologue: K(0), K(1)
    cp16(kbuf[0] + so0, Kp + go0);
    cp16(kbuf[0] + so1, Kp + go1);
    CP_COMMIT();
    cp16(kbuf[1] + so0, Kp + 64*HD + go0);
    cp16(kbuf[1] + so1, Kp + 64*HD + go1);
    CP_COMMIT();

    __syncthreads();   // Q + mask visible to all warps

    // ---- hoisted Q fragments (invariant across all k tiles, both passes) ----
    uint32_t aq[4][4];
    #pragma unroll
    for (int k16 = 0; k16 < 4; k16++)
        ldsm4(aq[k16], qb + ((w*16+lrow16)*STR + k16*16 + lchunk)*2);

    // ---------------- PASS 1: rowsum of ex2(QK) ----------------
    float ls0a = 0.f, ls0b = 0.f, ls1a = 0.f, ls1b = 0.f;
    int cur = 0, pf = 2;
    for (int kt = 0; kt < 32; kt++){
        if (kt == 31) { CP_WAIT0(); } else { CP_WAIT1(); }
        __syncthreads();
        if (kt < 30){
            const __half* src = Kp + (size_t)(kt+2)*64*HD;
            cp16(kbuf[pf] + so0, src + go0);
            cp16(kbuf[pf] + so1, src + go1);
            CP_COMMIT();
        }
        uint32_t kba = kbuf[cur];
        int kb0 = kt*64;

        float c[8][4];
        #pragma unroll
        for (int ni=0; ni<8; ni++){ c[ni][0]=0.f; c[ni][1]=0.f; c[ni][2]=0.f; c[ni][3]=0.f; }
        #pragma unroll
        for (int k16 = 0; k16 < 4; k16++){
            uint32_t bq[4][4];
            #pragma unroll
            for (int nq=0; nq<4; nq++)
                ldsm4(bq[nq], kba + ((nq*16+bnrow)*STR + k16*16 + lchunk)*2);
            #pragma unroll
            for (int nq=0; nq<4; nq++)
                #pragma unroll
                for (int sub=0; sub<2; sub++){
                    uint32_t bb[2] = { bq[nq][sub], bq[nq][sub+2] };
                    mma16(c[nq*2+sub], aq[k16], bb);
                }
        }
        #pragma unroll
        for (int ni=0; ni<8; ni++){
            int col = kb0 + ni*8 + 2*t;
            int2 mm = *reinterpret_cast<const int2*>(Msk + col);
            bool m0 = (mm.x == 0), m1 = (mm.y == 0);
            if (ni & 1){
                ls0b += (m0?0.f:ex2f(c[ni][0])) + (m1?0.f:ex2f(c[ni][1]));
                ls1b += (m0?0.f:ex2f(c[ni][2])) + (m1?0.f:ex2f(c[ni][3]));
            } else {
                ls0a += (m0?0.f:ex2f(c[ni][0])) + (m1?0.f:ex2f(c[ni][1]));
                ls1a += (m0?0.f:ex2f(c[ni][2])) + (m1?0.f:ex2f(c[ni][3]));
            }
        }
        cur = (cur==2) ? 0 : cur+1;
        pf  = (pf==2)  ? 0 : pf+1;
    }
    float lsum0 = ls0a + ls0b, lsum1 = ls1a + ls1b;
    lsum0 += __shfl_xor_sync(0xffffffffu, lsum0, 1);
    lsum0 += __shfl_xor_sync(0xffffffffu, lsum0, 2);
    lsum1 += __shfl_xor_sync(0xffffffffu, lsum1, 1);
    lsum1 += __shfl_xor_sync(0xffffffffu, lsum1, 2);
    float il0 = 1.0f / lsum0;
    float il1 = 1.0f / lsum1;

    __syncthreads();   // all warps done with pass-1 buffers before reuse

    // ---------------- PASS 2: normalized P -> attn + PV ----------------
    float co[8][4];
    #pragma unroll
    for (int ni=0; ni<8; ni++){ co[ni][0]=0.f; co[ni][1]=0.f; co[ni][2]=0.f; co[ni][3]=0.f; }

    cp16(kbuf[0] + so0, Kp + go0);
    cp16(kbuf[0] + so1, Kp + go1);
    cp16(vbuf[0] + so0, Vp + go0);
    cp16(vbuf[0] + so1, Vp + go1);
    CP_COMMIT();
    cp16(kbuf[1] + so0, Kp + 64*HD + go0);
    cp16(kbuf[1] + so1, Kp + 64*HD + go1);
    cp16(vbuf[1] + so0, Vp + 64*HD + go0);
    cp16(vbuf[1] + so1, Vp + 64*HD + go1);
    CP_COMMIT();

    float* ar0 = attn + ((size_t)bh*SEQ + q0 + row0)*SEQ;
    float* ar1 = ar0 + (size_t)8*SEQ;

    cur = 0; pf = 2;
    for (int kt = 0; kt < 32; kt++){
        if (kt == 31) { CP_WAIT0(); } else { CP_WAIT1(); }
        __syncthreads();
        if (kt < 30){
            const __half* ksrc = Kp + (size_t)(kt+2)*64*HD;
            const __half* vsrc = Vp + (size_t)(kt+2)*64*HD;
            cp16(kbuf[pf] + so0, ksrc + go0);
            cp16(kbuf[pf] + so1, ksrc + go1);
            cp16(vbuf[pf] + so0, vsrc + go0);
            cp16(vbuf[pf] + so1, vsrc + go1);
            CP_COMMIT();
        }
        uint32_t kba = kbuf[cur], vba = vbuf[cur];
        int kb0 = kt*64;

        float c[8][4];
        #pragma unroll
        for (int ni=0; ni<8; ni++){ c[ni][0]=0.f; c[ni][1]=0.f; c[ni][2]=0.f; c[ni][3]=0.f; }
        #pragma unroll
        for (int k16 = 0; k16 < 4; k16++){
            uint32_t bq[4][4];
            #pragma unroll
            for (int nq=0; nq<4; nq++)
                ldsm4(bq[nq], kba + ((nq*16+bnrow)*STR + k16*16 + lchunk)*2);
            #pragma unroll
            for (int nq=0; nq<4; nq++)
                #pragma unroll
                for (int sub=0; sub<2; sub++){
                    uint32_t bb[2] = { bq[nq][sub], bq[nq][sub+2] };
                    mma16(c[nq*2+sub], aq[k16], bb);
                }
        }

        uint32_t ph0[8], ph1[8];
        #pragma unroll
        for (int ni=0; ni<8; ni++){
            int cl = ni*8 + 2*t;
            int col = kb0 + cl;
            int2 mm = *reinterpret_cast<const int2*>(Msk + col);
            bool m0 = (mm.x == 0), m1 = (mm.y == 0);
            float p00 = m0 ? 0.f : ex2f(c[ni][0]) * il0;
            float p01 = m1 ? 0.f : ex2f(c[ni][1]) * il0;
            float p10 = m0 ? 0.f : ex2f(c[ni][2]) * il1;
            float p11 = m1 ? 0.f : ex2f(c[ni][3]) * il1;
            __stcs(reinterpret_cast<float2*>(ar0 + col), make_float2(p00, p01));
            __stcs(reinterpret_cast<float2*>(ar1 + col), make_float2(p10, p11));
            __half2 h0v = __floats2half2_rn(p00, p01);
            __half2 h1v = __floats2half2_rn(p10, p11);
            ph0[ni] = *(uint32_t*)&h0v;
            ph1[ni] = *(uint32_t*)&h1v;
        }

        #pragma unroll
        for (int k16 = 0; k16 < 4; k16++){
            uint32_t ap[4] = { ph0[2*k16], ph1[2*k16], ph0[2*k16+1], ph1[2*k16+1] };
            #pragma unroll
            for (int ni2 = 0; ni2 < 4; ni2++){
                uint32_t bv4[4];
                ldsm4t(bv4, vba + ((k16*16+lrow16)*STR + ni2*16 + lchunk)*2);
                mma16(co[ni2*2],   ap, bv4);
                mma16(co[ni2*2+1], ap, bv4+2);
            }
        }
        cur = (cur==2) ? 0 : cur+1;
        pf  = (pf==2)  ? 0 : pf+1;
    }

    __half* Op = g_Oh + ((size_t)b*SEQ + q0 + w*16)*EMBED + h*HD;
    #pragma unroll
    for (int ni=0; ni<8; ni++){
        int cl = ni*8 + 2*t;
        __half2 o0 = __floats2half2_rn(co[ni][0], co[ni][1]);
        __half2 o1 = __floats2half2_rn(co[ni][2], co[ni][3]);
        *reinterpret_cast<__half2*>(Op + (size_t)g*EMBED + cl)     = o0;
        *reinterpret_cast<__half2*>(Op + (size_t)(g+8)*EMBED + cl) = o1;
    }
}

// ============================================================================
// Kernel 3: out = g_Oh @ Wo.T + bo   (M=8192, N=512, K=512)  fp16 MMA
// ============================================================================
#define OP_SMEM_BYTES (128*STR*2 + 64*STR*2)

__global__ __launch_bounds__(256)
void oproj_kernel(const float* __restrict__ Wo, const float* __restrict__ bo,
                  float* __restrict__ out){
    extern __shared__ char osmc[];
    uint32_t ab = saddr(osmc);
    uint32_t bb_ = saddr(osmc + 128*STR*2);
    __half* Bh = (__half*)(osmc + 128*STR*2);

    int tid = threadIdx.x, lane = tid & 31, warp = tid >> 5;
    int wm = warp >> 1, wn = warp & 1, rm = wm*32;
    int g = lane >> 2, t = lane & 3;
    int lrow16 = lane & 15;
    int lchunk = (lane >> 4) << 3;
    int bnrow  = (lane & 7) + ((lane >> 3) & 1) * 8;
    int n0 = blockIdx.x * 64;
    int m0 = blockIdx.y * 128;

    float c[2][4][4];
    #pragma unroll
    for (int mi=0;mi<2;mi++)
        #pragma unroll
        for (int ni=0;ni<4;ni++)
            { c[mi][ni][0]=0.f;c[mi][ni][1]=0.f;c[mi][ni][2]=0.f;c[mi][ni][3]=0.f; }

    const __half* Ap = g_Oh + (size_t)m0*EMBED;

    for (int k0 = 0; k0 < 512; k0 += 64){
        __syncthreads();
        #pragma unroll
        for (int j = 0; j < 4; j++){
            int lin = tid + j*256;
            int row = lin >> 3, ch = lin & 7;
            uint4 v = *reinterpret_cast<const uint4*>(Ap + (size_t)row*EMBED + k0 + ch*8);
            *reinterpret_cast<uint4*>(osmc + row*(STR*2) + ch*16) = v;
        }
        #pragma unroll
        for (int j = 0; j < 2; j++){
            int lin = tid + j*256;
            int row = lin >> 3, c8 = (lin & 7) * 8;
            const float* src = Wo + (size_t)(n0+row)*512 + k0 + c8;
            float4 v0 = *reinterpret_cast<const float4*>(src);
            float4 v1 = *reinterpret_cast<const float4*>(src + 4);
            __half2 h0 = __floats2half2_rn(v0.x, v0.y);
            __half2 h1 = __floats2half2_rn(v0.z, v0.w);
            __half2 h2 = __floats2half2_rn(v1.x, v1.y);
            __half2 h3 = __floats2half2_rn(v1.z, v1.w);
            uint4 u; u.x = *(uint32_t*)&h0; u.y = *(uint32_t*)&h1;
            u.z = *(uint32_t*)&h2; u.w = *(uint32_t*)&h3;
            *reinterpret_cast<uint4*>((char*)Bh + row*(STR*2) + c8*2) = u;
        }
        __syncthreads();

        #pragma unroll
        for (int k16 = 0; k16 < 4; k16++){
            uint32_t a[2][4];
            #pragma unroll
            for (int mi=0; mi<2; mi++)
                ldsm4(a[mi], ab + ((rm+mi*16+lrow16)*STR + k16*16 + lchunk)*2);
            uint32_t bq[2][4];
            #pragma unroll
            for (int pr=0; pr<2; pr++)
                ldsm4(bq[pr], bb_ + ((wn*32+pr*16+bnrow)*STR + k16*16 + lchunk)*2);
            #pragma unroll
            for (int mi=0; mi<2; mi++)
                #pragma unroll
                for (int pr=0; pr<2; pr++)
                    #pragma unroll
                    for (int sub=0; sub<2; sub++){
                        uint32_t bb2[2] = { bq[pr][sub], bq[pr][sub+2] };
                        mma16(c[mi][pr*2+sub], a[mi], bb2);
                    }
        }
    }
    #pragma unroll
    for (int mi=0;mi<2;mi++)
        #pragma unroll
        for (int half=0; half<2; half++){
            int row = rm + mi*16 + half*8 + g;
            #pragma unroll
            for (int ni=0; ni<4; ni++){
                int col = wn*32 + ni*8 + 2*t;
                float2 bv = *reinterpret_cast<const float2*>(bo + n0 + col);
                *reinterpret_cast<float2*>(out + (size_t)(m0+row)*512 + n0 + col) =
                    make_float2(c[mi][ni][half*2] + bv.x, c[mi][ni][half*2+1] + bv.y);
            }
        }
}

// ============================================================================
// launch
// ============================================================================
extern "C" void kernel_launch(void* const* d_in, const int* in_sizes, int n_in,
                              void* d_out, int out_size){
    (void)in_sizes; (void)n_in; (void)out_size;
    const float* values = (const float*)d_in[0];
    const float* keys   = (const float*)d_in[1];
    const float* query  = (const float*)d_in[2];
    const int*   mask   = (const int*)d_in[3];
    const float* Wv     = (const float*)d_in[4];
    const float* Wk     = (const float*)d_in[5];
    const float* Wq     = (const float*)d_in[6];
    const float* Wo     = (const float*)d_in[7];
    const float* bo     = (const float*)d_in[8];

    float* out  = (float*)d_out;                              // [B,S,E]
    float* attn = out + (size_t)BATCH*SEQ*EMBED;              // [B,H,S,S]

    __half *qptr, *kptr, *vptr;
    cudaGetSymbolAddress((void**)&qptr, g_Qh);
    cudaGetSymbolAddress((void**)&kptr, g_Kh);
    cudaGetSymbolAddress((void**)&vptr, g_Vh);

    cudaFuncSetAttribute(attn_kernel, cudaFuncAttributeMaxDynamicSharedMemorySize,
                         SM_TOTAL);
    cudaFuncSetAttribute(oproj_kernel, cudaFuncAttributeMaxDynamicSharedMemorySize,
                         OP_SMEM_BYTES);
    cudaFuncSetAttribute(proj_kernel, cudaFuncAttributeMaxDynamicSharedMemorySize,
                         PJ_TOTAL);

    proj_kernel<<<dim3(SEQ/128, BATCH*NHEADS, 3), 256, PJ_TOTAL>>>(
        query, keys, values, Wq, Wk, Wv, qptr, kptr, vptr);

    attn_kernel<<<dim3(SEQ/128, BATCH*NHEADS), 256, SM_TOTAL>>>(mask, attn);

    oproj_kernel<<<dim3(EMBED/64, (BATCH*SEQ)/128), 256, OP_SMEM_BYTES>>>(Wo, bo, out);
}

// round 16
// speedup vs baseline: 1.0371x; 1.0012x over previous
#include <cuda_runtime.h>
#include <cuda_fp16.h>
#include <cstdint>

#define NHEADS 8
#define EMBED  512
#define HD     64
#define BATCH  4
#define SEQ    2048
#define STR    72   // smem tile stride in halves (144B rows)

// ---- scratch (allocation-free: __device__ globals) ----
__device__ __half g_Kh[BATCH*NHEADS*SEQ*HD];
__device__ __half g_Vh[BATCH*NHEADS*SEQ*HD];
__device__ __half g_Oh[BATCH*SEQ*EMBED];       // attention output pre-Wo (fp16)

__device__ __forceinline__ uint32_t saddr(const void* p){
    return (uint32_t)__cvta_generic_to_shared(p);
}
__device__ __forceinline__ void cp16(uint32_t d, const void* s){
    asm volatile("cp.async.cg.shared.global [%0], [%1], 16;\n" :: "r"(d), "l"(s));
}
#define CP_COMMIT() asm volatile("cp.async.commit_group;\n")
#define CP_WAIT0()  asm volatile("cp.async.wait_group 0;\n")
#define CP_WAIT1()  asm volatile("cp.async.wait_group 1;\n")

__device__ __forceinline__ void ldsm4(uint32_t* r, uint32_t a){
    asm volatile("ldmatrix.sync.aligned.m8n8.x4.shared.b16 {%0,%1,%2,%3}, [%4];\n"
        : "=r"(r[0]),"=r"(r[1]),"=r"(r[2]),"=r"(r[3]) : "r"(a));
}
__device__ __forceinline__ void ldsm4t(uint32_t* r, uint32_t a){
    asm volatile("ldmatrix.sync.aligned.m8n8.x4.trans.shared.b16 {%0,%1,%2,%3}, [%4];\n"
        : "=r"(r[0]),"=r"(r[1]),"=r"(r[2]),"=r"(r[3]) : "r"(a));
}
__device__ __forceinline__ void mma16(float* c, const uint32_t* a, const uint32_t* b){
    asm volatile(
        "mma.sync.aligned.m16n8k16.row.col.f32.f16.f16.f32 "
        "{%0,%1,%2,%3}, {%4,%5,%6,%7}, {%8,%9}, {%0,%1,%2,%3};\n"
        : "+f"(c[0]),"+f"(c[1]),"+f"(c[2]),"+f"(c[3])
        : "r"(a[0]),"r"(a[1]),"r"(a[2]),"r"(a[3]),"r"(b[0]),"r"(b[1]));
}
__device__ __forceinline__ float ex2f(float x){
    float y; asm("ex2.approx.f32 %0, %1;" : "=f"(y) : "f"(x)); return y;
}
__device__ __forceinline__ uint32_t packh2(float a, float b){
    __half2 h = __floats2half2_rn(a, b);
    return *(uint32_t*)&h;
}

// ============================================================================
// Kernel 1: K/V per-head projection via fp16 MMA (Q is fused into attn).
// CTA = 128 seq rows x one (b,h) x one of K/V (z). 8 warps x 16 rows.
// ============================================================================
#define PJ_X  0
#define PJ_W  18432
#define PJ_TOTAL (18432 + 9216)

__global__ __launch_bounds__(256)
void proj_kernel(const float* __restrict__ Xk, const float* __restrict__ Xv,
                 const float* __restrict__ Wk, const float* __restrict__ Wv,
                 __half* __restrict__ Yk, __half* __restrict__ Yv){
    extern __shared__ char psm[];
    uint32_t xb = saddr(psm + PJ_X);
    uint32_t wb = saddr(psm + PJ_W);

    int z = blockIdx.z;
    const float* X = (z==0) ? Xk : Xv;
    const float* W = (z==0) ? Wk : Wv;
    __half*      Y = (z==0) ? Yk : Yv;

    int tid = threadIdx.x, lane = tid & 31, w = tid >> 5;
    int g = lane >> 2, t = lane & 3;
    int lrow16 = lane & 15;
    int lchunk = (lane >> 4) << 3;
    int bnrow  = (lane & 7) + ((lane >> 3) & 1) * 8;
    int bh = blockIdx.y; int b = bh >> 3; int h = bh & 7;
    int s0 = blockIdx.x * 128;

    #pragma unroll
    for (int j = 0; j < 8; j++){
        int lin = tid + j*256;
        int row = lin >> 4, c4 = (lin & 15) << 2;
        float4 v = *reinterpret_cast<const float4*>(
            X + (((size_t)b*SEQ + s0 + row)*NHEADS + h)*HD + c4);
        uint2 u; u.x = packh2(v.x, v.y); u.y = packh2(v.z, v.w);
        *reinterpret_cast<uint2*>(psm + PJ_X + (row*STR + c4)*2) = u;
    }
    #pragma unroll
    for (int j = 0; j < 4; j++){
        int lin = tid + j*256;
        int row = lin >> 4, c4 = (lin & 15) << 2;
        float4 v = *reinterpret_cast<const float4*>(W + (size_t)row*64 + c4);
        uint2 u; u.x = packh2(v.x, v.y); u.y = packh2(v.z, v.w);
        *reinterpret_cast<uint2*>(psm + PJ_W + (row*STR + c4)*2) = u;
    }
    __syncthreads();

    float c[8][4];
    #pragma unroll
    for (int ni=0; ni<8; ni++){ c[ni][0]=0.f; c[ni][1]=0.f; c[ni][2]=0.f; c[ni][3]=0.f; }
    #pragma unroll
    for (int k16 = 0; k16 < 4; k16++){
        uint32_t a[4];
        ldsm4(a, xb + ((w*16+lrow16)*STR + k16*16 + lchunk)*2);
        uint32_t bq[4][4];
        #pragma unroll
        for (int nq=0; nq<4; nq++)
            ldsm4(bq[nq], wb + ((nq*16+bnrow)*STR + k16*16 + lchunk)*2);
        #pragma unroll
        for (int nq=0; nq<4; nq++)
            #pragma unroll
            for (int sub=0; sub<2; sub++){
                uint32_t bb[2] = { bq[nq][sub], bq[nq][sub+2] };
                mma16(c[nq*2+sub], a, bb);
            }
    }

    __half* Yp = Y + ((size_t)bh*SEQ + s0 + w*16)*HD;
    #pragma unroll
    for (int ni=0; ni<8; ni++){
        int cl = ni*8 + 2*t;
        uint32_t o0 = packh2(c[ni][0], c[ni][1]);
        uint32_t o1 = packh2(c[ni][2], c[ni][3]);
        *reinterpret_cast<uint32_t*>(Yp + (size_t)g*HD + cl)     = o0;
        *reinterpret_cast<uint32_t*>(Yp + (size_t)(g+8)*HD + cl) = o1;
    }
}

// ============================================================================
// Kernel 2: two-pass fused attention with FUSED Q PROJECTION.
// Prologue: project this CTA's 128 Q rows (raw query @ Wq.T, scaled by
// log2(e)/sqrt(512)); the proj C-fragments pack directly into QK A-fragments
// (same register correspondence as the proven P->PV path). No Q smem tile,
// no Q gmem round-trip. Then: pass 1 rowsum of ex2(QK); pass 2 normalized
// P -> attn (streaming) + register-direct PV. 3-stage cp.async ring.
// grid (16, 32), 256 threads, 91136 B smem -> 2 CTAs/SM.
// ============================================================================
#define SM_X    0
#define SM_W    18432
#define SM_K0   27648
#define SM_V0   55296
#define SM_MSK  82944
#define SM_TOTAL 91136
#define KBUF    9216

__global__ __launch_bounds__(256, 2)
void attn_kernel(const float* __restrict__ query, const float* __restrict__ Wq,
                 const int* __restrict__ mask, float* __restrict__ attn){
    extern __shared__ char smc[];
    int* Msk = (int*)(smc + SM_MSK);
    uint32_t xb = saddr(smc + SM_X);
    uint32_t wb = saddr(smc + SM_W);
    uint32_t kbuf[3] = { saddr(smc + SM_K0), saddr(smc + SM_K0 + KBUF),
                         saddr(smc + SM_K0 + 2*KBUF) };
    uint32_t vbuf[3] = { saddr(smc + SM_V0), saddr(smc + SM_V0 + KBUF),
                         saddr(smc + SM_V0 + 2*KBUF) };

    int tid = threadIdx.x, lane = tid & 31, w = tid >> 5;
    int g = lane >> 2, t = lane & 3;
    int lrow16 = lane & 15;
    int lchunk = (lane >> 4) << 3;
    int bnrow  = (lane & 7) + ((lane >> 3) & 1) * 8;
    int bh = blockIdx.y, b = bh >> 3, h = bh & 7;
    int q0 = blockIdx.x * 128;
    const __half* Kp = g_Kh + (size_t)bh*SEQ*HD;
    const __half* Vp = g_Vh + (size_t)bh*SEQ*HD;
    const int* mrow_g = mask + (size_t)b*SEQ;
    int row0 = w*16 + g;

    int ldr0 = tid >> 3, ldc = tid & 7;
    int ldr1 = ldr0 + 32;
    uint32_t so0 = (ldr0*STR + ldc*8)*2;
    uint32_t so1 = (ldr1*STR + ldc*8)*2;
    size_t   go0 = (size_t)ldr0*HD + ldc*8;
    size_t   go1 = (size_t)ldr1*HD + ldc*8;

    // ---- prologue: start K(0), K(1) prefetch immediately ----
    cp16(kbuf[0] + so0, Kp + go0);
    cp16(kbuf[0] + so1, Kp + go1);
    CP_COMMIT();
    cp16(kbuf[1] + so0, Kp + 64*HD + go0);
    cp16(kbuf[1] + so1, Kp + 64*HD + go1);
    CP_COMMIT();

    // ---- raw query tile (fp32 -> fp16 smem), Wq tile, mask row ----
    #pragma unroll
    for (int j = 0; j < 8; j++){
        int lin = tid + j*256;
        int row = lin >> 4, c4 = (lin & 15) << 2;
        float4 v = *reinterpret_cast<const float4*>(
            query + (((size_t)b*SEQ + q0 + row)*NHEADS + h)*HD + c4);
        uint2 u; u.x = packh2(v.x, v.y); u.y = packh2(v.z, v.w);
        *reinterpret_cast<uint2*>(smc + SM_X + (row*STR + c4)*2) = u;
    }
    #pragma unroll
    for (int j = 0; j < 4; j++){
        int lin = tid + j*256;
        int row = lin >> 4, c4 = (lin & 15) << 2;
        float4 v = *reinterpret_cast<const float4*>(Wq + (size_t)row*64 + c4);
        uint2 u; u.x = packh2(v.x, v.y); u.y = packh2(v.z, v.w);
        *reinterpret_cast<uint2*>(smc + SM_W + (row*STR + c4)*2) = u;
    }
    #pragma unroll
    for (int j = 0; j < 2; j++){
        int lin = tid + j*256;
        int4 v = *reinterpret_cast<const int4*>(mrow_g + lin*4);
        *reinterpret_cast<int4*>(Msk + lin*4) = v;
    }
    __syncthreads();   // X/W/mask visible

    // ---- fused Q projection: C-fragments -> QK A-fragments (registers) ----
    const float sc = 0.06375881311003162f;   // log2(e)/sqrt(512)
    uint32_t aq[4][4];
    {
        float cq[8][4];
        #pragma unroll
        for (int ni=0; ni<8; ni++){ cq[ni][0]=0.f; cq[ni][1]=0.f; cq[ni][2]=0.f; cq[ni][3]=0.f; }
        #pragma unroll
        for (int k16 = 0; k16 < 4; k16++){
            uint32_t a[4];
            ldsm4(a, xb + ((w*16+lrow16)*STR + k16*16 + lchunk)*2);
            uint32_t bq[4][4];
            #pragma unroll
            for (int nq=0; nq<4; nq++)
                ldsm4(bq[nq], wb + ((nq*16+bnrow)*STR + k16*16 + lchunk)*2);
            #pragma unroll
            for (int nq=0; nq<4; nq++)
                #pragma unroll
                for (int sub=0; sub<2; sub++){
                    uint32_t bb[2] = { bq[nq][sub], bq[nq][sub+2] };
                    mma16(cq[nq*2+sub], a, bb);
                }
        }
        // pack (row g / g+8, col ni*8+2t) C-frags into A-frags, same as PV path
        #pragma unroll
        for (int k16 = 0; k16 < 4; k16++){
            aq[k16][0] = packh2(cq[2*k16][0]*sc,   cq[2*k16][1]*sc);     // row g,  k 2t,2t+1
            aq[k16][1] = packh2(cq[2*k16][2]*sc,   cq[2*k16][3]*sc);     // row g+8
            aq[k16][2] = packh2(cq[2*k16+1][0]*sc, cq[2*k16+1][1]*sc);   // row g,  k 8+2t
            aq[k16][3] = packh2(cq[2*k16+1][2]*sc, cq[2*k16+1][3]*sc);   // row g+8
        }
    }

    // ---------------- PASS 1: rowsum of ex2(QK) ----------------
    float ls0a = 0.f, ls0b = 0.f, ls1a = 0.f, ls1b = 0.f;
    int cur = 0, pf = 2;
    for (int kt = 0; kt < 32; kt++){
        if (kt == 31) { CP_WAIT0(); } else { CP_WAIT1(); }
        __syncthreads();
        if (kt < 30){
            const __half* src = Kp + (size_t)(kt+2)*64*HD;
            cp16(kbuf[pf] + so0, src + go0);
            cp16(kbuf[pf] + so1, src + go1);
            CP_COMMIT();
        }
        uint32_t kba = kbuf[cur];
        int kb0 = kt*64;

        float c[8][4];
        #pragma unroll
        for (int ni=0; ni<8; ni++){ c[ni][0]=0.f; c[ni][1]=0.f; c[ni][2]=0.f; c[ni][3]=0.f; }
        #pragma unroll
        for (int k16 = 0; k16 < 4; k16++){
            uint32_t bq[4][4];
            #pragma unroll
            for (int nq=0; nq<4; nq++)
                ldsm4(bq[nq], kba + ((nq*16+bnrow)*STR + k16*16 + lchunk)*2);
            #pragma unroll
            for (int nq=0; nq<4; nq++)
                #pragma unroll
                for (int sub=0; sub<2; sub++){
                    uint32_t bb[2] = { bq[nq][sub], bq[nq][sub+2] };
                    mma16(c[nq*2+sub], aq[k16], bb);
                }
        }
        #pragma unroll
        for (int ni=0; ni<8; ni++){
            int col = kb0 + ni*8 + 2*t;
            int2 mm = *reinterpret_cast<const int2*>(Msk + col);
            bool m0 = (mm.x == 0), m1 = (mm.y == 0);
            if (ni & 1){
                ls0b += (m0?0.f:ex2f(c[ni][0])) + (m1?0.f:ex2f(c[ni][1]));
                ls1b += (m0?0.f:ex2f(c[ni][2])) + (m1?0.f:ex2f(c[ni][3]));
            } else {
                ls0a += (m0?0.f:ex2f(c[ni][0])) + (m1?0.f:ex2f(c[ni][1]));
                ls1a += (m0?0.f:ex2f(c[ni][2])) + (m1?0.f:ex2f(c[ni][3]));
            }
        }
        cur = (cur==2) ? 0 : cur+1;
        pf  = (pf==2)  ? 0 : pf+1;
    }
    float lsum0 = ls0a + ls0b, lsum1 = ls1a + ls1b;
    lsum0 += __shfl_xor_sync(0xffffffffu, lsum0, 1);
    lsum0 += __shfl_xor_sync(0xffffffffu, lsum0, 2);
    lsum1 += __shfl_xor_sync(0xffffffffu, lsum1, 1);
    lsum1 += __shfl_xor_sync(0xffffffffu, lsum1, 2);
    float il0 = 1.0f / lsum0;
    float il1 = 1.0f / lsum1;

    __syncthreads();   // all warps done with pass-1 buffers before reuse

    // ---------------- PASS 2: normalized P -> attn + PV ----------------
    float co[8][4];
    #pragma unroll
    for (int ni=0; ni<8; ni++){ co[ni][0]=0.f; co[ni][1]=0.f; co[ni][2]=0.f; co[ni][3]=0.f; }

    cp16(kbuf[0] + so0, Kp + go0);
    cp16(kbuf[0] + so1, Kp + go1);
    cp16(vbuf[0] + so0, Vp + go0);
    cp16(vbuf[0] + so1, Vp + go1);
    CP_COMMIT();
    cp16(kbuf[1] + so0, Kp + 64*HD + go0);
    cp16(kbuf[1] + so1, Kp + 64*HD + go1);
    cp16(vbuf[1] + so0, Vp + 64*HD + go0);
    cp16(vbuf[1] + so1, Vp + 64*HD + go1);
    CP_COMMIT();

    float* ar0 = attn + ((size_t)bh*SEQ + q0 + row0)*SEQ;
    float* ar1 = ar0 + (size_t)8*SEQ;

    cur = 0; pf = 2;
    for (int kt = 0; kt < 32; kt++){
        if (kt == 31) { CP_WAIT0(); } else { CP_WAIT1(); }
        __syncthreads();
        if (kt < 30){
            const __half* ksrc = Kp + (size_t)(kt+2)*64*HD;
            const __half* vsrc = Vp + (size_t)(kt+2)*64*HD;
            cp16(kbuf[pf] + so0, ksrc + go0);
            cp16(kbuf[pf] + so1, ksrc + go1);
            cp16(vbuf[pf] + so0, vsrc + go0);
            cp16(vbuf[pf] + so1, vsrc + go1);
            CP_COMMIT();
        }
        uint32_t kba = kbuf[cur], vba = vbuf[cur];
        int kb0 = kt*64;

        float c[8][4];
        #pragma unroll
        for (int ni=0; ni<8; ni++){ c[ni][0]=0.f; c[ni][1]=0.f; c[ni][2]=0.f; c[ni][3]=0.f; }
        #pragma unroll
        for (int k16 = 0; k16 < 4; k16++){
            uint32_t bq[4][4];
            #pragma unroll
            for (int nq=0; nq<4; nq++)
                ldsm4(bq[nq], kba + ((nq*16+bnrow)*STR + k16*16 + lchunk)*2);
            #pragma unroll
            for (int nq=0; nq<4; nq++)
                #pragma unroll
                for (int sub=0; sub<2; sub++){
                    uint32_t bb[2] = { bq[nq][sub], bq[nq][sub+2] };
                    mma16(c[nq*2+sub], aq[k16], bb);
                }
        }

        uint32_t ph0[8], ph1[8];
        #pragma unroll
        for (int ni=0; ni<8; ni++){
            int cl = ni*8 + 2*t;
            int col = kb0 + cl;
            int2 mm = *reinterpret_cast<const int2*>(Msk + col);
            bool m0 = (mm.x == 0), m1 = (mm.y == 0);
            float p00 = m0 ? 0.f : ex2f(c[ni][0]) * il0;
            float p01 = m1 ? 0.f : ex2f(c[ni][1]) * il0;
            float p10 = m0 ? 0.f : ex2f(c[ni][2]) * il1;
            float p11 = m1 ? 0.f : ex2f(c[ni][3]) * il1;
            __stcs(reinterpret_cast<float2*>(ar0 + col), make_float2(p00, p01));
            __stcs(reinterpret_cast<float2*>(ar1 + col), make_float2(p10, p11));
            ph0[ni] = packh2(p00, p01);
            ph1[ni] = packh2(p10, p11);
        }

        #pragma unroll
        for (int k16 = 0; k16 < 4; k16++){
            uint32_t ap[4] = { ph0[2*k16], ph1[2*k16], ph0[2*k16+1], ph1[2*k16+1] };
            #pragma unroll
            for (int ni2 = 0; ni2 < 4; ni2++){
                uint32_t bv4[4];
                ldsm4t(bv4, vba + ((k16*16+lrow16)*STR + ni2*16 + lchunk)*2);
                mma16(co[ni2*2],   ap, bv4);
                mma16(co[ni2*2+1], ap, bv4+2);
            }
        }
        cur = (cur==2) ? 0 : cur+1;
        pf  = (pf==2)  ? 0 : pf+1;
    }

    __half* Op = g_Oh + ((size_t)b*SEQ + q0 + w*16)*EMBED + h*HD;
    #pragma unroll
    for (int ni=0; ni<8; ni++){
        int cl = ni*8 + 2*t;
        uint32_t o0 = packh2(co[ni][0], co[ni][1]);
        uint32_t o1 = packh2(co[ni][2], co[ni][3]);
        *reinterpret_cast<uint32_t*>(Op + (size_t)g*EMBED + cl)     = o0;
        *reinterpret_cast<uint32_t*>(Op + (size_t)(g+8)*EMBED + cl) = o1;
    }
}

// ============================================================================
// Kernel 3: out = g_Oh @ Wo.T + bo   (M=8192, N=512, K=512)  fp16 MMA
// CTA tile 128x128 (n-tile doubled: halves A-redundancy traffic).
// grid (4, 64), 256 threads, 8 warps x 16 rows x n=128. 36864 B smem.
// ============================================================================
#define OP_SMEM_BYTES (128*STR*2 + 128*STR*2)

__global__ __launch_bounds__(256, 2)
void oproj_kernel(const float* __restrict__ Wo, const float* __restrict__ bo,
                  float* __restrict__ out){
    extern __shared__ char osmc[];
    uint32_t ab = saddr(osmc);
    uint32_t bb_ = saddr(osmc + 128*STR*2);
    char* Bh = osmc + 128*STR*2;

    int tid = threadIdx.x, lane = tid & 31, w = tid >> 5;
    int g = lane >> 2, t = lane & 3;
    int lrow16 = lane & 15;
    int lchunk = (lane >> 4) << 3;
    int bnrow  = (lane & 7) + ((lane >> 3) & 1) * 8;
    int n0 = blockIdx.x * 128;
    int m0 = blockIdx.y * 128;

    float c[16][4];
    #pragma unroll
    for (int ni=0; ni<16; ni++){ c[ni][0]=0.f; c[ni][1]=0.f; c[ni][2]=0.f; c[ni][3]=0.f; }

    const __half* Ap = g_Oh + (size_t)m0*EMBED;

    for (int k0 = 0; k0 < 512; k0 += 64){
        __syncthreads();
        // A tile: 128 rows x 64 k (fp16 direct copy)
        #pragma unroll
        for (int j = 0; j < 4; j++){
            int lin = tid + j*256;
            int row = lin >> 3, ch = lin & 7;
            uint4 v = *reinterpret_cast<const uint4*>(Ap + (size_t)row*EMBED + k0 + ch*8);
            *reinterpret_cast<uint4*>(osmc + row*(STR*2) + ch*16) = v;
        }
        // B tile: Wo 128 rows x 64 k, fp32 -> fp16
        #pragma unroll
        for (int j = 0; j < 4; j++){
            int lin = tid + j*256;
            int row = lin >> 3, c8 = (lin & 7) * 8;
            const float* src = Wo + (size_t)(n0+row)*512 + k0 + c8;
            float4 v0 = *reinterpret_cast<const float4*>(src);
            float4 v1 = *reinterpret_cast<const float4*>(src + 4);
            uint4 u; u.x = packh2(v0.x, v0.y); u.y = packh2(v0.z, v0.w);
            u.z = packh2(v1.x, v1.y); u.w = packh2(v1.z, v1.w);
            *reinterpret_cast<uint4*>(Bh + row*(STR*2) + c8*2) = u;
        }
        __syncthreads();

        #pragma unroll
        for (int k16 = 0; k16 < 4; k16++){
            uint32_t a[4];
            ldsm4(a, ab + ((w*16+lrow16)*STR + k16*16 + lchunk)*2);
            #pragma unroll
            for (int nq=0; nq<8; nq++){
                uint32_t bq4[4];
                ldsm4(bq4, bb_ + ((nq*16+bnrow)*STR + k16*16 + lchunk)*2);
                uint32_t b0[2] = { bq4[0], bq4[2] };
                uint32_t b1[2] = { bq4[1], bq4[3] };
                mma16(c[nq*2],   a, b0);
                mma16(c[nq*2+1], a, b1);
            }
        }
    }
    int mrow = m0 + w*16 + g;
    #pragma unroll
    for (int ni=0; ni<16; ni++){
        int col = ni*8 + 2*t;
        float2 bv = *reinterpret_cast<const float2*>(bo + n0 + col);
        *reinterpret_cast<float2*>(out + (size_t)mrow*512 + n0 + col) =
            make_float2(c[ni][0] + bv.x, c[ni][1] + bv.y);
        *reinterpret_cast<float2*>(out + (size_t)(mrow+8)*512 + n0 + col) =
            make_float2(c[ni][2] + bv.x, c[ni][3] + bv.y);
    }
}

// ============================================================================
// launch
// ============================================================================
extern "C" void kernel_launch(void* const* d_in, const int* in_sizes, int n_in,
                              void* d_out, int out_size){
    (void)in_sizes; (void)n_in; (void)out_size;
    const float* values = (const float*)d_in[0];
    const float* keys   = (const float*)d_in[1];
    const float* query  = (const float*)d_in[2];
    const int*   mask   = (const int*)d_in[3];
    const float* Wv     = (const float*)d_in[4];
    const float* Wk     = (const float*)d_in[5];
    const float* Wq     = (const float*)d_in[6];
    const float* Wo     = (const float*)d_in[7];
    const float* bo     = (const float*)d_in[8];

    float* out  = (float*)d_out;                              // [B,S,E]
    float* attn = out + (size_t)BATCH*SEQ*EMBED;              // [B,H,S,S]

    __half *kptr, *vptr;
    cudaGetSymbolAddress((void**)&kptr, g_Kh);
    cudaGetSymbolAddress((void**)&vptr, g_Vh);

    cudaFuncSetAttribute(attn_kernel, cudaFuncAttributeMaxDynamicSharedMemorySize,
                         SM_TOTAL);
    cudaFuncSetAttribute(oproj_kernel, cudaFuncAttributeMaxDynamicSharedMemorySize,
                         OP_SMEM_BYTES);
    cudaFuncSetAttribute(proj_kernel, cudaFuncAttributeMaxDynamicSharedMemorySize,
                         PJ_TOTAL);

    proj_kernel<<<dim3(SEQ/128, BATCH*NHEADS, 2), 256, PJ_TOTAL>>>(
        keys, values, Wk, Wv, kptr, vptr);

    attn_kernel<<<dim3(SEQ/128, BATCH*NHEADS), 256, SM_TOTAL>>>(query, Wq, mask, attn);

    oproj_kernel<<<dim3(EMBED/128, (BATCH*SEQ)/128), 256, OP_SMEM_BYTES>>>(Wo, bo, out);
}

// round 17
// speedup vs baseline: 1.1618x; 1.1202x over previous
#include <cuda_runtime.h>
#include <cuda_fp16.h>
#include <cstdint>

#define NHEADS 8
#define EMBED  512
#define HD     64
#define BATCH  4
#define SEQ    2048
#define STR    72   // smem tile stride in halves (144B rows)

// ---- scratch (allocation-free: __device__ globals) ----
__device__ __half g_Kh[BATCH*NHEADS*SEQ*HD];
__device__ __half g_Vh[BATCH*NHEADS*SEQ*HD];
__device__ __half g_Oh[BATCH*SEQ*EMBED];       // attention output pre-Wo (fp16)

__device__ __forceinline__ uint32_t saddr(const void* p){
    return (uint32_t)__cvta_generic_to_shared(p);
}
__device__ __forceinline__ void cp16(uint32_t d, const void* s){
    asm volatile("cp.async.cg.shared.global [%0], [%1], 16;\n" :: "r"(d), "l"(s));
}
#define CP_COMMIT() asm volatile("cp.async.commit_group;\n")
#define CP_WAIT0()  asm volatile("cp.async.wait_group 0;\n")
#define CP_WAIT1()  asm volatile("cp.async.wait_group 1;\n")

__device__ __forceinline__ void ldsm4(uint32_t* r, uint32_t a){
    asm volatile("ldmatrix.sync.aligned.m8n8.x4.shared.b16 {%0,%1,%2,%3}, [%4];\n"
        : "=r"(r[0]),"=r"(r[1]),"=r"(r[2]),"=r"(r[3]) : "r"(a));
}
__device__ __forceinline__ void ldsm4t(uint32_t* r, uint32_t a){
    asm volatile("ldmatrix.sync.aligned.m8n8.x4.trans.shared.b16 {%0,%1,%2,%3}, [%4];\n"
        : "=r"(r[0]),"=r"(r[1]),"=r"(r[2]),"=r"(r[3]) : "r"(a));
}
__device__ __forceinline__ void mma16(float* c, const uint32_t* a, const uint32_t* b){
    asm volatile(
        "mma.sync.aligned.m16n8k16.row.col.f32.f16.f16.f32 "
        "{%0,%1,%2,%3}, {%4,%5,%6,%7}, {%8,%9}, {%0,%1,%2,%3};\n"
        : "+f"(c[0]),"+f"(c[1]),"+f"(c[2]),"+f"(c[3])
        : "r"(a[0]),"r"(a[1]),"r"(a[2]),"r"(a[3]),"r"(b[0]),"r"(b[1]));
}
__device__ __forceinline__ float ex2f(float x){
    float y; asm("ex2.approx.f32 %0, %1;" : "=f"(y) : "f"(x)); return y;
}
__device__ __forceinline__ uint32_t ex2h2(uint32_t x){
    uint32_t y; asm("ex2.approx.f16x2 %0, %1;" : "=r"(y) : "r"(x)); return y;
}
__device__ __forceinline__ uint32_t packh2(float a, float b){
    __half2 h = __floats2half2_rn(a, b);
    return *(uint32_t*)&h;
}

// ============================================================================
// Kernel 1: K/V per-head projection via fp16 MMA (Q is fused into attn).
// CTA = 128 seq rows x one (b,h) x one of K/V (z). 8 warps x 16 rows.
// ============================================================================
#define PJ_X  0
#define PJ_W  18432
#define PJ_TOTAL (18432 + 9216)

__global__ __launch_bounds__(256)
void proj_kernel(const float* __restrict__ Xk, const float* __restrict__ Xv,
                 const float* __restrict__ Wk, const float* __restrict__ Wv,
                 __half* __restrict__ Yk, __half* __restrict__ Yv){
    extern __shared__ char psm[];
    uint32_t xb = saddr(psm + PJ_X);
    uint32_t wb = saddr(psm + PJ_W);

    int z = blockIdx.z;
    const float* X = (z==0) ? Xk : Xv;
    const float* W = (z==0) ? Wk : Wv;
    __half*      Y = (z==0) ? Yk : Yv;

    int tid = threadIdx.x, lane = tid & 31, w = tid >> 5;
    int g = lane >> 2, t = lane & 3;
    int lrow16 = lane & 15;
    int lchunk = (lane >> 4) << 3;
    int bnrow  = (lane & 7) + ((lane >> 3) & 1) * 8;
    int bh = blockIdx.y; int b = bh >> 3; int h = bh & 7;
    int s0 = blockIdx.x * 128;

    #pragma unroll
    for (int j = 0; j < 8; j++){
        int lin = tid + j*256;
        int row = lin >> 4, c4 = (lin & 15) << 2;
        float4 v = *reinterpret_cast<const float4*>(
            X + (((size_t)b*SEQ + s0 + row)*NHEADS + h)*HD + c4);
        uint2 u; u.x = packh2(v.x, v.y); u.y = packh2(v.z, v.w);
        *reinterpret_cast<uint2*>(psm + PJ_X + (row*STR + c4)*2) = u;
    }
    #pragma unroll
    for (int j = 0; j < 4; j++){
        int lin = tid + j*256;
        int row = lin >> 4, c4 = (lin & 15) << 2;
        float4 v = *reinterpret_cast<const float4*>(W + (size_t)row*64 + c4);
        uint2 u; u.x = packh2(v.x, v.y); u.y = packh2(v.z, v.w);
        *reinterpret_cast<uint2*>(psm + PJ_W + (row*STR + c4)*2) = u;
    }
    __syncthreads();

    float c[8][4];
    #pragma unroll
    for (int ni=0; ni<8; ni++){ c[ni][0]=0.f; c[ni][1]=0.f; c[ni][2]=0.f; c[ni][3]=0.f; }
    #pragma unroll
    for (int k16 = 0; k16 < 4; k16++){
        uint32_t a[4];
        ldsm4(a, xb + ((w*16+lrow16)*STR + k16*16 + lchunk)*2);
        uint32_t bq[4][4];
        #pragma unroll
        for (int nq=0; nq<4; nq++)
            ldsm4(bq[nq], wb + ((nq*16+bnrow)*STR + k16*16 + lchunk)*2);
        #pragma unroll
        for (int nq=0; nq<4; nq++)
            #pragma unroll
            for (int sub=0; sub<2; sub++){
                uint32_t bb[2] = { bq[nq][sub], bq[nq][sub+2] };
                mma16(c[nq*2+sub], a, bb);
            }
    }

    __half* Yp = Y + ((size_t)bh*SEQ + s0 + w*16)*HD;
    #pragma unroll
    for (int ni=0; ni<8; ni++){
        int cl = ni*8 + 2*t;
        uint32_t o0 = packh2(c[ni][0], c[ni][1]);
        uint32_t o1 = packh2(c[ni][2], c[ni][3]);
        *reinterpret_cast<uint32_t*>(Yp + (size_t)g*HD + cl)     = o0;
        *reinterpret_cast<uint32_t*>(Yp + (size_t)(g+8)*HD + cl) = o1;
    }
}

// ============================================================================
// Kernel 2: two-pass fused attention with fused Q projection.
// Mask held in smem as ADDITIVE float (0 / -1e30): ex2(c+am) gives exact 0
// for masked columns (no predicates/selects).
// Pass 1 uses ex2.approx.f16x2 (half the MUFU ops; error washes out in the
// 2048-term rowsum). Pass 2 keeps fp32 ex2 for the stored P values.
// grid (16, 32), 256 threads, 91136 B smem -> 2 CTAs/SM.
// ============================================================================
#define SM_X    0
#define SM_W    18432
#define SM_K0   27648
#define SM_V0   55296
#define SM_AM   82944
#define SM_TOTAL 91136
#define KBUF    9216

__global__ __launch_bounds__(256, 2)
void attn_kernel(const float* __restrict__ query, const float* __restrict__ Wq,
                 const int* __restrict__ mask, float* __restrict__ attn){
    extern __shared__ char smc[];
    float* Am = (float*)(smc + SM_AM);
    uint32_t xb = saddr(smc + SM_X);
    uint32_t wb = saddr(smc + SM_W);
    uint32_t kbuf[3] = { saddr(smc + SM_K0), saddr(smc + SM_K0 + KBUF),
                         saddr(smc + SM_K0 + 2*KBUF) };
    uint32_t vbuf[3] = { saddr(smc + SM_V0), saddr(smc + SM_V0 + KBUF),
                         saddr(smc + SM_V0 + 2*KBUF) };

    int tid = threadIdx.x, lane = tid & 31, w = tid >> 5;
    int g = lane >> 2, t = lane & 3;
    int lrow16 = lane & 15;
    int lchunk = (lane >> 4) << 3;
    int bnrow  = (lane & 7) + ((lane >> 3) & 1) * 8;
    int bh = blockIdx.y, b = bh >> 3, h = bh & 7;
    int q0 = blockIdx.x * 128;
    const __half* Kp = g_Kh + (size_t)bh*SEQ*HD;
    const __half* Vp = g_Vh + (size_t)bh*SEQ*HD;
    const int* mrow_g = mask + (size_t)b*SEQ;
    int row0 = w*16 + g;

    int ldr0 = tid >> 3, ldc = tid & 7;
    int ldr1 = ldr0 + 32;
    uint32_t so0 = (ldr0*STR + ldc*8)*2;
    uint32_t so1 = (ldr1*STR + ldc*8)*2;
    size_t   go0 = (size_t)ldr0*HD + ldc*8;
    size_t   go1 = (size_t)ldr1*HD + ldc*8;

    // ---- prologue: start K(0), K(1) prefetch immediately ----
    cp16(kbuf[0] + so0, Kp + go0);
    cp16(kbuf[0] + so1, Kp + go1);
    CP_COMMIT();
    cp16(kbuf[1] + so0, Kp + 64*HD + go0);
    cp16(kbuf[1] + so1, Kp + 64*HD + go1);
    CP_COMMIT();

    // ---- raw query tile (fp32 -> fp16 smem), Wq tile, additive mask ----
    #pragma unroll
    for (int j = 0; j < 8; j++){
        int lin = tid + j*256;
        int row = lin >> 4, c4 = (lin & 15) << 2;
        float4 v = *reinterpret_cast<const float4*>(
            query + (((size_t)b*SEQ + q0 + row)*NHEADS + h)*HD + c4);
        uint2 u; u.x = packh2(v.x, v.y); u.y = packh2(v.z, v.w);
        *reinterpret_cast<uint2*>(smc + SM_X + (row*STR + c4)*2) = u;
    }
    #pragma unroll
    for (int j = 0; j < 4; j++){
        int lin = tid + j*256;
        int row = lin >> 4, c4 = (lin & 15) << 2;
        float4 v = *reinterpret_cast<const float4*>(Wq + (size_t)row*64 + c4);
        uint2 u; u.x = packh2(v.x, v.y); u.y = packh2(v.z, v.w);
        *reinterpret_cast<uint2*>(smc + SM_W + (row*STR + c4)*2) = u;
    }
    #pragma unroll
    for (int j = 0; j < 2; j++){
        int lin = tid + j*256;
        int4 v = *reinterpret_cast<const int4*>(mrow_g + lin*4);
        float4 a;
        a.x = v.x ? 0.f : -1e30f;
        a.y = v.y ? 0.f : -1e30f;
        a.z = v.z ? 0.f : -1e30f;
        a.w = v.w ? 0.f : -1e30f;
        *reinterpret_cast<float4*>(Am + lin*4) = a;
    }
    __syncthreads();   // X/W/mask visible

    // ---- fused Q projection: C-fragments -> QK A-fragments (registers) ----
    const float sc = 0.06375881311003162f;   // log2(e)/sqrt(512)
    uint32_t aq[4][4];
    {
        float cq[8][4];
        #pragma unroll
        for (int ni=0; ni<8; ni++){ cq[ni][0]=0.f; cq[ni][1]=0.f; cq[ni][2]=0.f; cq[ni][3]=0.f; }
        #pragma unroll
        for (int k16 = 0; k16 < 4; k16++){
            uint32_t a[4];
            ldsm4(a, xb + ((w*16+lrow16)*STR + k16*16 + lchunk)*2);
            uint32_t bq[4][4];
            #pragma unroll
            for (int nq=0; nq<4; nq++)
                ldsm4(bq[nq], wb + ((nq*16+bnrow)*STR + k16*16 + lchunk)*2);
            #pragma unroll
            for (int nq=0; nq<4; nq++)
                #pragma unroll
                for (int sub=0; sub<2; sub++){
                    uint32_t bb[2] = { bq[nq][sub], bq[nq][sub+2] };
                    mma16(cq[nq*2+sub], a, bb);
                }
        }
        #pragma unroll
        for (int k16 = 0; k16 < 4; k16++){
            aq[k16][0] = packh2(cq[2*k16][0]*sc,   cq[2*k16][1]*sc);
            aq[k16][1] = packh2(cq[2*k16][2]*sc,   cq[2*k16][3]*sc);
            aq[k16][2] = packh2(cq[2*k16+1][0]*sc, cq[2*k16+1][1]*sc);
            aq[k16][3] = packh2(cq[2*k16+1][2]*sc, cq[2*k16+1][3]*sc);
        }
    }

    // ---------------- PASS 1: rowsum of ex2(QK) [f16x2 MUFU] ----------------
    float ls0a = 0.f, ls0b = 0.f, ls1a = 0.f, ls1b = 0.f;
    int cur = 0, pf = 2;
    for (int kt = 0; kt < 32; kt++){
        if (kt == 31) { CP_WAIT0(); } else { CP_WAIT1(); }
        __syncthreads();
        if (kt < 30){
            const __half* src = Kp + (size_t)(kt+2)*64*HD;
            cp16(kbuf[pf] + so0, src + go0);
            cp16(kbuf[pf] + so1, src + go1);
            CP_COMMIT();
        }
        uint32_t kba = kbuf[cur];
        int kb0 = kt*64;

        float c[8][4];
        #pragma unroll
        for (int ni=0; ni<8; ni++){ c[ni][0]=0.f; c[ni][1]=0.f; c[ni][2]=0.f; c[ni][3]=0.f; }
        #pragma unroll
        for (int k16 = 0; k16 < 4; k16++){
            uint32_t bq[4][4];
            #pragma unroll
            for (int nq=0; nq<4; nq++)
                ldsm4(bq[nq], kba + ((nq*16+bnrow)*STR + k16*16 + lchunk)*2);
            #pragma unroll
            for (int nq=0; nq<4; nq++)
                #pragma unroll
                for (int sub=0; sub<2; sub++){
                    uint32_t bb[2] = { bq[nq][sub], bq[nq][sub+2] };
                    mma16(c[nq*2+sub], aq[k16], bb);
                }
        }
        #pragma unroll
        for (int ni=0; ni<8; ni++){
            int col = kb0 + ni*8 + 2*t;
            float2 am = *reinterpret_cast<const float2*>(Am + col);
            uint32_t e0 = ex2h2(packh2(c[ni][0]+am.x, c[ni][1]+am.y));
            uint32_t e1 = ex2h2(packh2(c[ni][2]+am.x, c[ni][3]+am.y));
            float2 f0 = __half22float2(*reinterpret_cast<__half2*>(&e0));
            float2 f1 = __half22float2(*reinterpret_cast<__half2*>(&e1));
            if (ni & 1){ ls0b += f0.x + f0.y; ls1b += f1.x + f1.y; }
            else       { ls0a += f0.x + f0.y; ls1a += f1.x + f1.y; }
        }
        cur = (cur==2) ? 0 : cur+1;
        pf  = (pf==2)  ? 0 : pf+1;
    }
    float lsum0 = ls0a + ls0b, lsum1 = ls1a + ls1b;
    lsum0 += __shfl_xor_sync(0xffffffffu, lsum0, 1);
    lsum0 += __shfl_xor_sync(0xffffffffu, lsum0, 2);
    lsum1 += __shfl_xor_sync(0xffffffffu, lsum1, 1);
    lsum1 += __shfl_xor_sync(0xffffffffu, lsum1, 2);
    float il0 = 1.0f / lsum0;
    float il1 = 1.0f / lsum1;

    __syncthreads();   // all warps done with pass-1 buffers before reuse

    // ---------------- PASS 2: normalized P -> attn + PV ----------------
    float co[8][4];
    #pragma unroll
    for (int ni=0; ni<8; ni++){ co[ni][0]=0.f; co[ni][1]=0.f; co[ni][2]=0.f; co[ni][3]=0.f; }

    cp16(kbuf[0] + so0, Kp + go0);
    cp16(kbuf[0] + so1, Kp + go1);
    cp16(vbuf[0] + so0, Vp + go0);
    cp16(vbuf[0] + so1, Vp + go1);
    CP_COMMIT();
    cp16(kbuf[1] + so0, Kp + 64*HD + go0);
    cp16(kbuf[1] + so1, Kp + 64*HD + go1);
    cp16(vbuf[1] + so0, Vp + 64*HD + go0);
    cp16(vbuf[1] + so1, Vp + 64*HD + go1);
    CP_COMMIT();

    float* ar0 = attn + ((size_t)bh*SEQ + q0 + row0)*SEQ;
    float* ar1 = ar0 + (size_t)8*SEQ;

    cur = 0; pf = 2;
    for (int kt = 0; kt < 32; kt++){
        if (kt == 31) { CP_WAIT0(); } else { CP_WAIT1(); }
        __syncthreads();
        if (kt < 30){
            const __half* ksrc = Kp + (size_t)(kt+2)*64*HD;
            const __half* vsrc = Vp + (size_t)(kt+2)*64*HD;
            cp16(kbuf[pf] + so0, ksrc + go0);
            cp16(kbuf[pf] + so1, ksrc + go1);
            cp16(vbuf[pf] + so0, vsrc + go0);
            cp16(vbuf[pf] + so1, vsrc + go1);
            CP_COMMIT();
        }
        uint32_t kba = kbuf[cur], vba = vbuf[cur];
        int kb0 = kt*64;

        float c[8][4];
        #pragma unroll
        for (int ni=0; ni<8; ni++){ c[ni][0]=0.f; c[ni][1]=0.f; c[ni][2]=0.f; c[ni][3]=0.f; }
        #pragma unroll
        for (int k16 = 0; k16 < 4; k16++){
            uint32_t bq[4][4];
            #pragma unroll
            for (int nq=0; nq<4; nq++)
                ldsm4(bq[nq], kba + ((nq*16+bnrow)*STR + k16*16 + lchunk)*2);
            #pragma unroll
            for (int nq=0; nq<4; nq++)
                #pragma unroll
                for (int sub=0; sub<2; sub++){
                    uint32_t bb[2] = { bq[nq][sub], bq[nq][sub+2] };
                    mma16(c[nq*2+sub], aq[k16], bb);
                }
        }

        uint32_t ph0[8], ph1[8];
        #pragma unroll
        for (int ni=0; ni<8; ni++){
            int cl = ni*8 + 2*t;
            int col = kb0 + cl;
            float2 am = *reinterpret_cast<const float2*>(Am + col);
            float p00 = ex2f(c[ni][0]+am.x) * il0;
            float p01 = ex2f(c[ni][1]+am.y) * il0;
            float p10 = ex2f(c[ni][2]+am.x) * il1;
            float p11 = ex2f(c[ni][3]+am.y) * il1;
            __stcs(reinterpret_cast<float2*>(ar0 + col), make_float2(p00, p01));
            __stcs(reinterpret_cast<float2*>(ar1 + col), make_float2(p10, p11));
            ph0[ni] = packh2(p00, p01);
            ph1[ni] = packh2(p10, p11);
        }

        #pragma unroll
        for (int k16 = 0; k16 < 4; k16++){
            uint32_t ap[4] = { ph0[2*k16], ph1[2*k16], ph0[2*k16+1], ph1[2*k16+1] };
            #pragma unroll
            for (int ni2 = 0; ni2 < 4; ni2++){
                uint32_t bv4[4];
                ldsm4t(bv4, vba + ((k16*16+lrow16)*STR + ni2*16 + lchunk)*2);
                mma16(co[ni2*2],   ap, bv4);
                mma16(co[ni2*2+1], ap, bv4+2);
            }
        }
        cur = (cur==2) ? 0 : cur+1;
        pf  = (pf==2)  ? 0 : pf+1;
    }

    __half* Op = g_Oh + ((size_t)b*SEQ + q0 + w*16)*EMBED + h*HD;
    #pragma unroll
    for (int ni=0; ni<8; ni++){
        int cl = ni*8 + 2*t;
        uint32_t o0 = packh2(co[ni][0], co[ni][1]);
        uint32_t o1 = packh2(co[ni][2], co[ni][3]);
        *reinterpret_cast<uint32_t*>(Op + (size_t)g*EMBED + cl)     = o0;
        *reinterpret_cast<uint32_t*>(Op + (size_t)(g+8)*EMBED + cl) = o1;
    }
}

// ============================================================================
// Kernel 3: out = g_Oh @ Wo.T + bo   (M=8192, N=512, K=512)  fp16 MMA
// CTA tile 128x128, grid (4, 64), 256 threads. 36864 B smem.
// ============================================================================
#define OP_SMEM_BYTES (128*STR*2 + 128*STR*2)

__global__ __launch_bounds__(256, 2)
void oproj_kernel(const float* __restrict__ Wo, const float* __restrict__ bo,
                  float* __restrict__ out){
    extern __shared__ char osmc[];
    uint32_t ab = saddr(osmc);
    uint32_t bb_ = saddr(osmc + 128*STR*2);
    char* Bh = osmc + 128*STR*2;

    int tid = threadIdx.x, lane = tid & 31, w = tid >> 5;
    int g = lane >> 2, t = lane & 3;
    int lrow16 = lane & 15;
    int lchunk = (lane >> 4) << 3;
    int bnrow  = (lane & 7) + ((lane >> 3) & 1) * 8;
    int n0 = blockIdx.x * 128;
    int m0 = blockIdx.y * 128;

    float c[16][4];
    #pragma unroll
    for (int ni=0; ni<16; ni++){ c[ni][0]=0.f; c[ni][1]=0.f; c[ni][2]=0.f; c[ni][3]=0.f; }

    const __half* Ap = g_Oh + (size_t)m0*EMBED;

    for (int k0 = 0; k0 < 512; k0 += 64){
        __syncthreads();
        #pragma unroll
        for (int j = 0; j < 4; j++){
            int lin = tid + j*256;
            int row = lin >> 3, ch = lin & 7;
            uint4 v = *reinterpret_cast<const uint4*>(Ap + (size_t)row*EMBED + k0 + ch*8);
            *reinterpret_cast<uint4*>(osmc + row*(STR*2) + ch*16) = v;
        }
        #pragma unroll
        for (int j = 0; j < 4; j++){
            int lin = tid + j*256;
            int row = lin >> 3, c8 = (lin & 7) * 8;
            const float* src = Wo + (size_t)(n0+row)*512 + k0 + c8;
            float4 v0 = *reinterpret_cast<const float4*>(src);
            float4 v1 = *reinterpret_cast<const float4*>(src + 4);
            uint4 u; u.x = packh2(v0.x, v0.y); u.y = packh2(v0.z, v0.w);
            u.z = packh2(v1.x, v1.y); u.w = packh2(v1.z, v1.w);
            *reinterpret_cast<uint4*>(Bh + row*(STR*2) + c8*2) = u;
        }
        __syncthreads();

        #pragma unroll
        for (int k16 = 0; k16 < 4; k16++){
            uint32_t a[4];
            ldsm4(a, ab + ((w*16+lrow16)*STR + k16*16 + lchunk)*2);
            #pragma unroll
            for (int nq=0; nq<8; nq++){
                uint32_t bq4[4];
                ldsm4(bq4, bb_ + ((nq*16+bnrow)*STR + k16*16 + lchunk)*2);
                uint32_t b0[2] = { bq4[0], bq4[2] };
                uint32_t b1[2] = { bq4[1], bq4[3] };
                mma16(c[nq*2],   a, b0);
                mma16(c[nq*2+1], a, b1);
            }
        }
    }
    int mrow = m0 + w*16 + g;
    #pragma unroll
    for (int ni=0; ni<16; ni++){
        int col = ni*8 + 2*t;
        float2 bv = *reinterpret_cast<const float2*>(bo + n0 + col);
        *reinterpret_cast<float2*>(out + (size_t)mrow*512 + n0 + col) =
            make_float2(c[ni][0] + bv.x, c[ni][1] + bv.y);
        *reinterpret_cast<float2*>(out + (size_t)(mrow+8)*512 + n0 + col) =
            make_float2(c[ni][2] + bv.x, c[ni][3] + bv.y);
    }
}

// ============================================================================
// launch
// ============================================================================
extern "C" void kernel_launch(void* const* d_in, const int* in_sizes, int n_in,
                              void* d_out, int out_size){
    (void)in_sizes; (void)n_in; (void)out_size;
    const float* values = (const float*)d_in[0];
    const float* keys   = (const float*)d_in[1];
    const float* query  = (const float*)d_in[2];
    const int*   mask   = (const int*)d_in[3];
    const float* Wv     = (const float*)d_in[4];
    const float* Wk     = (const float*)d_in[5];
    const float* Wq     = (const float*)d_in[6];
    const float* Wo     = (const float*)d_in[7];
    const float* bo     = (const float*)d_in[8];

    float* out  = (float*)d_out;                              // [B,S,E]
    float* attn = out + (size_t)BATCH*SEQ*EMBED;              // [B,H,S,S]

    __half *kptr, *vptr;
    cudaGetSymbolAddress((void**)&kptr, g_Kh);
    cudaGetSymbolAddress((void**)&vptr, g_Vh);

    cudaFuncSetAttribute(attn_kernel, cudaFuncAttributeMaxDynamicSharedMemorySize,
                         SM_TOTAL);
    cudaFuncSetAttribute(oproj_kernel, cudaFuncAttributeMaxDynamicSharedMemorySize,
                         OP_SMEM_BYTES);
    cudaFuncSetAttribute(proj_kernel, cudaFuncAttributeMaxDynamicSharedMemorySize,
                         PJ_TOTAL);

    proj_kernel<<<dim3(SEQ/128, BATCH*NHEADS, 2), 256, PJ_TOTAL>>>(
        keys, values, Wk, Wv, kptr, vptr);

    attn_kernel<<<dim3(SEQ/128, BATCH*NHEADS), 256, SM_TOTAL>>>(query, Wq, mask, attn);

    oproj_kernel<<<dim3(EMBED/128, (BATCH*SEQ)/128), 256, OP_SMEM_BYTES>>>(Wo, bo, out);
}